// round 8
// baseline (speedup 1.0000x reference)
#include <cuda_runtime.h>
#include <cuda_bf16.h>
#include <math.h>
#include <stdint.h>

// Problem constants
#define B_  4
#define T_  1024
#define D_  1024
#define H_  16
#define HD  64
#define BH  (B_*H_)     // 64
#define M_  (B_*T_)     // 4096

// Scratch (static device globals — no allocation)
__device__ float g_gate[BH*T_];               // [bh][t]
__device__ float g_pb[H_*2048];               // [h][rel+1023]

// bf16 split buffers
__device__ __nv_bfloat16 g_a_hi[(size_t)M_*D_];   // activations hi (hs, later ctx)
__device__ __nv_bfloat16 g_a_lo[(size_t)M_*D_];
__device__ __nv_bfloat16 g_w_hi[(size_t)4*D_*D_]; // 4 weight matrices hi
__device__ __nv_bfloat16 g_w_lo[(size_t)4*D_*D_];
// q/k/v in [bh][t][d] bf16 hi/lo
__device__ __nv_bfloat16 g_qh[(size_t)BH*T_*HD];
__device__ __nv_bfloat16 g_ql[(size_t)BH*T_*HD];
__device__ __nv_bfloat16 g_kh[(size_t)BH*T_*HD];
__device__ __nv_bfloat16 g_kl[(size_t)BH*T_*HD];
__device__ __nv_bfloat16 g_vh[(size_t)BH*T_*HD];
__device__ __nv_bfloat16 g_vl[(size_t)BH*T_*HD];

// ---------------------------------------------------------------------------
// PTX helpers
// ---------------------------------------------------------------------------
__device__ __forceinline__ uint32_t smem_u32(const void* p) {
    uint32_t a;
    asm("{ .reg .u64 t; cvta.to.shared.u64 t, %1; cvt.u32.u64 %0, t; }" : "=r"(a) : "l"(p));
    return a;
}
__device__ __forceinline__ void ldmx4(uint32_t* r, uint32_t addr) {
    asm volatile("ldmatrix.sync.aligned.m8n8.x4.shared.b16 {%0,%1,%2,%3}, [%4];"
        : "=r"(r[0]), "=r"(r[1]), "=r"(r[2]), "=r"(r[3]) : "r"(addr));
}
__device__ __forceinline__ void ldmx4t(uint32_t* r, uint32_t addr) {
    asm volatile("ldmatrix.sync.aligned.m8n8.x4.trans.shared.b16 {%0,%1,%2,%3}, [%4];"
        : "=r"(r[0]), "=r"(r[1]), "=r"(r[2]), "=r"(r[3]) : "r"(addr));
}
__device__ __forceinline__ void mma16816(float* c, const uint32_t* a, const uint32_t* b) {
    asm volatile("mma.sync.aligned.m16n8k16.row.col.f32.bf16.bf16.f32 "
        "{%0,%1,%2,%3}, {%4,%5,%6,%7}, {%8,%9}, {%0,%1,%2,%3};"
        : "+f"(c[0]), "+f"(c[1]), "+f"(c[2]), "+f"(c[3])
        : "r"(a[0]), "r"(a[1]), "r"(a[2]), "r"(a[3]), "r"(b[0]), "r"(b[1]));
}
__device__ __forceinline__ void cpasync16(uint32_t dst, const void* src) {
    asm volatile("cp.async.cg.shared.global [%0], [%1], 16;" :: "r"(dst), "l"(src));
}
#define CP_COMMIT()  asm volatile("cp.async.commit_group;" ::: "memory")
#define CP_WAIT(n)   asm volatile("cp.async.wait_group %0;" :: "n"(n) : "memory")
#define SWZ(o) ((o) ^ (((o) >> 3) & 0x70))

// split pair of floats into bf16x2 hi and lo words
__device__ __forceinline__ void split2(float x, float y, uint32_t& h, uint32_t& l) {
    __nv_bfloat162 hh = __floats2bfloat162_rn(x, y);
    float hx = __low2float(hh), hy = __high2float(hh);
    __nv_bfloat162 ll = __floats2bfloat162_rn(x - hx, y - hy);
    h = *(uint32_t*)&hh;
    l = *(uint32_t*)&ll;
}

// ---------------------------------------------------------------------------
// Split fp32 -> bf16 hi/lo (single tensor)
// ---------------------------------------------------------------------------
__global__ void split_kernel(const float* __restrict__ x,
                             __nv_bfloat16* __restrict__ hi,
                             __nv_bfloat16* __restrict__ lo, int n4)
{
    int i = blockIdx.x * blockDim.x + threadIdx.x;
    if (i >= n4) return;
    float4 v = ((const float4*)x)[i];
    uint32_t h0, l0, h1, l1;
    split2(v.x, v.y, h0, l0);
    split2(v.z, v.w, h1, l1);
    ((uint32_t*)hi)[2*i+0] = h0; ((uint32_t*)hi)[2*i+1] = h1;
    ((uint32_t*)lo)[2*i+0] = l0; ((uint32_t*)lo)[2*i+1] = l1;
}

// Fused split of the 4 weight matrices (blockIdx.y selects matrix)
__global__ void splitw_kernel(const float* __restrict__ w0,
                              const float* __restrict__ w1,
                              const float* __restrict__ w2,
                              const float* __restrict__ w3,
                              __nv_bfloat16* __restrict__ hi,
                              __nv_bfloat16* __restrict__ lo)
{
    const int mat = blockIdx.y;
    const float* x = (mat == 0) ? w0 : (mat == 1) ? w1 : (mat == 2) ? w2 : w3;
    const size_t base = (size_t)mat * D_ * D_;
    int i = blockIdx.x * blockDim.x + threadIdx.x;     // 0 .. D*D/4
    float4 v = ((const float4*)x)[i];
    uint32_t h0, l0, h1, l1;
    split2(v.x, v.y, h0, l0);
    split2(v.z, v.w, h1, l1);
    ((uint32_t*)(hi + base))[2*i+0] = h0; ((uint32_t*)(hi + base))[2*i+1] = h1;
    ((uint32_t*)(lo + base))[2*i+0] = l0; ((uint32_t*)(lo + base))[2*i+1] = l1;
}

// ---------------------------------------------------------------------------
// mma.sync projection GEMM core (unchanged)
// ---------------------------------------------------------------------------
#define SST    40
#define MAT_B  (128*SST*2)
#define STG_B  (4*MAT_B)
#define SMEMT  (2*STG_B)

__device__ __forceinline__ void proj_tile(
    const __nv_bfloat16* __restrict__ Ahi,
    const __nv_bfloat16* __restrict__ Alo,
    const __nv_bfloat16* __restrict__ Whi,
    const __nv_bfloat16* __restrict__ Wlo,
    const float* __restrict__ bias,
    float* __restrict__ outf,
    __nv_bfloat16* __restrict__ outh,
    __nv_bfloat16* __restrict__ outl,
    float scale, int remap, int m0, int n0, char* sm)
{
    const uint32_t sb = smem_u32(sm);
    const int tid = threadIdx.x;
    const int lane = tid & 31, wid = tid >> 5;
    const int wm = (wid >> 2) * 64, wn = (wid & 3) * 32;

    const __nv_bfloat16* gsrc[4];
    gsrc[0] = Ahi + (size_t)m0 * D_;
    gsrc[1] = Alo + (size_t)m0 * D_;
    gsrc[2] = Whi + (size_t)n0 * D_;
    gsrc[3] = Wlo + (size_t)n0 * D_;

    auto issue = [&](int kt, int s) {
        uint32_t sdst = sb + s * STG_B;
        #pragma unroll
        for (int mat = 0; mat < 4; mat++) {
            const __nv_bfloat16* g = gsrc[mat] + kt * 32;
            #pragma unroll
            for (int i = 0; i < 2; i++) {
                int idx = tid + i * 256;
                int r = idx >> 2, c = idx & 3;
                cpasync16(sdst + mat*MAT_B + (uint32_t)(r*SST + c*8)*2,
                          g + (size_t)r * D_ + c * 8);
            }
        }
        CP_COMMIT();
    };

    float acc[4][4][4];
    #pragma unroll
    for (int mt = 0; mt < 4; mt++)
        #pragma unroll
        for (int nt = 0; nt < 4; nt++)
            #pragma unroll
            for (int r = 0; r < 4; r++) acc[mt][nt][r] = 0.f;

    issue(0, 0);

    const int ar   = lane & 15;
    const int ac8  = lane >> 4;
    const int brow = (lane & 7) | ((lane & 16) >> 1);
    const int bc8  = (lane >> 3) & 1;

    for (int kt = 0; kt < 32; kt++) {
        const int s = kt & 1;
        if (kt + 1 < 32) { issue(kt + 1, s ^ 1); CP_WAIT(1); }
        else             { CP_WAIT(0); }
        __syncthreads();

        const uint32_t base = sb + s * STG_B;
        #pragma unroll
        for (int k16 = 0; k16 < 2; k16++) {
            uint32_t aH[4][4], aL[4][4];
            #pragma unroll
            for (int mt = 0; mt < 4; mt++) {
                uint32_t off = (uint32_t)((wm + mt*16 + ar)*SST + k16*16 + ac8*8) * 2;
                ldmx4(aH[mt], base + 0*MAT_B + off);
                ldmx4(aL[mt], base + 1*MAT_B + off);
            }
            #pragma unroll
            for (int np = 0; np < 2; np++) {
                uint32_t bh4[4], bl4[4];
                uint32_t off = (uint32_t)((wn + np*16 + brow)*SST + k16*16 + bc8*8) * 2;
                ldmx4(bh4, base + 2*MAT_B + off);
                ldmx4(bl4, base + 3*MAT_B + off);
                #pragma unroll
                for (int mt = 0; mt < 4; mt++) {
                    mma16816(acc[mt][2*np],   aH[mt], bh4);
                    mma16816(acc[mt][2*np],   aH[mt], bl4);
                    mma16816(acc[mt][2*np],   aL[mt], bh4);
                    mma16816(acc[mt][2*np+1], aH[mt], bh4+2);
                    mma16816(acc[mt][2*np+1], aH[mt], bl4+2);
                    mma16816(acc[mt][2*np+1], aL[mt], bh4+2);
                }
            }
        }
        __syncthreads();
    }

    const int tg = lane >> 2, tig = lane & 3;
    #pragma unroll
    for (int mt = 0; mt < 4; mt++)
        #pragma unroll
        for (int i2 = 0; i2 < 2; i2++) {
            int m = m0 + wm + mt*16 + tg + i2*8;
            #pragma unroll
            for (int nt = 0; nt < 4; nt++) {
                int n = n0 + wn + nt*8 + tig*2;
                float v0 = (acc[mt][nt][i2*2+0] + bias[n])   * scale;
                float v1 = (acc[mt][nt][i2*2+1] + bias[n+1]) * scale;
                if (remap) {
                    int b = m >> 10, t = m & 1023;
                    int h = n >> 6,  d = n & 63;
                    size_t off = (((size_t)(b*H_ + h)*T_ + t))*HD + d;
                    uint32_t hw, lw;
                    split2(v0, v1, hw, lw);
                    *(uint32_t*)(outh + off) = hw;
                    *(uint32_t*)(outl + off) = lw;
                } else {
                    *(float2*)(outf + (size_t)m*D_ + n) = make_float2(v0, v1);
                }
            }
        }
}

// Merged Q/K/V projection: grid.x = 24 (mat = x>>3, n-block = x&7), grid.y = 32.
__global__ __launch_bounds__(256, 2)
void qkv_mma_kernel(const __nv_bfloat16* __restrict__ Ahi,
                    const __nv_bfloat16* __restrict__ Alo,
                    const float* __restrict__ q_b,
                    const float* __restrict__ k_b,
                    const float* __restrict__ v_b)
{
    extern __shared__ char sm[];
    const int mat = blockIdx.x >> 3;
    const int n0  = (blockIdx.x & 7) * 128;
    const int m0  = blockIdx.y * 128;
    const size_t WSZ = (size_t)D_*D_;
    const float* bias = (mat == 0) ? q_b : (mat == 1) ? k_b : v_b;
    const float scale = (mat == 0) ? 0.125f : 1.0f;
    __nv_bfloat16* outh = (mat == 0) ? g_qh : (mat == 1) ? g_kh : g_vh;
    __nv_bfloat16* outl = (mat == 0) ? g_ql : (mat == 1) ? g_kl : g_vl;

    proj_tile(Ahi, Alo, g_w_hi + mat*WSZ, g_w_lo + mat*WSZ, bias,
              nullptr, outh, outl, scale, 1, m0, n0, sm);
}

// Output projection (fp32 out)
__global__ __launch_bounds__(256, 2)
void out_mma_kernel(const __nv_bfloat16* __restrict__ Ahi,
                    const __nv_bfloat16* __restrict__ Alo,
                    const float* __restrict__ bias,
                    float* __restrict__ out)
{
    extern __shared__ char sm[];
    const size_t WSZ = (size_t)D_*D_;
    proj_tile(Ahi, Alo, g_w_hi + 3*WSZ, g_w_lo + 3*WSZ, bias,
              out, nullptr, nullptr, 1.0f, 0,
              blockIdx.y * 128, blockIdx.x * 128, sm);
}

// ---------------------------------------------------------------------------
// Position-bias LUT
// ---------------------------------------------------------------------------
__global__ void pb_kernel(const float* __restrict__ rel_embed)
{
    int d = blockIdx.x * blockDim.x + threadIdx.x;
    if (d >= 2047) return;
    int rel = d - 1023;
    int rb  = (rel > 0) ? 160 : 0;
    int rp  = rel < 0 ? -rel : rel;
    int bucket;
    if (rp < 80) {
        bucket = rb + rp;
    } else {
        float t = logf((float)rp / 80.0f) / logf(10.0f);
        t = t * 80.0f;
        float v = 80.0f + t;
        int bi = (int)v;
        bucket = rb + (bi < 159 ? bi : 159);
    }
    #pragma unroll
    for (int h = 0; h < H_; h++)
        g_pb[h*2048 + d] = rel_embed[bucket*H_ + h];
}

// ---------------------------------------------------------------------------
// Gate
// ---------------------------------------------------------------------------
__global__ void gate_kernel(const float* __restrict__ hs,
                            const float* __restrict__ gw,
                            const float* __restrict__ gb,
                            const float* __restrict__ gc)
{
    int idx = blockIdx.x * blockDim.x + threadIdx.x;
    if (idx >= BH*T_) return;
    int t  = idx & (T_-1);
    int bh = idx >> 10;
    int h  = bh & (H_-1);
    int b  = bh >> 4;

    const float4* x = (const float4*)(hs + ((size_t)(b*T_+t))*D_ + h*HD);
    float p[8];
    #pragma unroll
    for (int e = 0; e < 8; e++) p[e] = 0.f;
    #pragma unroll
    for (int i = 0; i < 16; i++) {
        float4 xv = x[i];
        #pragma unroll
        for (int e = 0; e < 8; e++) {
            const float* w = gw + e*HD + i*4;
            p[e] += xv.x*w[0] + xv.y*w[1] + xv.z*w[2] + xv.w*w[3];
        }
    }
    float pa = p[0]+p[1]+p[2]+p[3] + gb[0]+gb[1]+gb[2]+gb[3];
    float pbv= p[4]+p[5]+p[6]+p[7] + gb[4]+gb[5]+gb[6]+gb[7];
    float ga  = 1.f/(1.f + expf(-pa));
    float gbs = 1.f/(1.f + expf(-pbv));
    g_gate[idx] = ga * (gbs * gc[h] - 1.f) + 2.f;
}

// ---------------------------------------------------------------------------
// Fused flash attention — 64-row KV tiles, 2 CTAs/SM.
// Q tile 128 (8 warps x 16 q-rows); 16 KV iterations of 64 keys.
// ---------------------------------------------------------------------------
#define FQ_B      16384                 // 128 x 64 bf16 (Q hi or lo)
#define FKV_B     8192                  // 64 x 64 bf16 (one matrix)
#define F_STG_B   (4*FKV_B)             // Kh,Kl,Vh,Vl = 32 KB
#define F_SM_KV   (2*FQ_B)
#define F_SM_PB   (F_SM_KV + 2*F_STG_B) // 98304
#define F_SMEMT   (F_SM_PB + 2*192*4)   // 99840

__global__ __launch_bounds__(256, 2)
void flash_kernel(__nv_bfloat16* __restrict__ outh,
                  __nv_bfloat16* __restrict__ outl)
{
    extern __shared__ char sm[];
    const uint32_t sb = smem_u32(sm);
    float* pb_s = (float*)(sm + F_SM_PB);

    const int tid  = threadIdx.x;
    const int lane = tid & 31, w = tid >> 5;
    const int qt = blockIdx.x, bh = blockIdx.y;
    const int b = bh >> 4, h = bh & 15;
    const size_t bhoff = (size_t)bh * T_ * HD;

    const __nv_bfloat16* gQh = g_qh + bhoff + (size_t)qt*128*HD;
    const __nv_bfloat16* gQl = g_ql + bhoff + (size_t)qt*128*HD;

    // ---- prologue: Q + KV stage 0 + pb slice 0 ----
    #pragma unroll
    for (int i = 0; i < 4; i++) {
        int idx = tid + i * 256;
        int r = idx >> 3, c = idx & 7;
        uint32_t off = SWZ((uint32_t)(r*128 + c*16));
        cpasync16(sb + off,        gQh + r*HD + c*8);
        cpasync16(sb + FQ_B + off, gQl + r*HD + c*8);
    }
    {
        const __nv_bfloat16* src[4] = { g_kh + bhoff, g_kl + bhoff,
                                        g_vh + bhoff, g_vl + bhoff };
        #pragma unroll
        for (int mat = 0; mat < 4; mat++)
            #pragma unroll
            for (int i = 0; i < 2; i++) {
                int idx = tid + i * 256;
                int r = idx >> 3, c = idx & 7;
                uint32_t off = SWZ((uint32_t)(r*128 + c*16));
                cpasync16(sb + F_SM_KV + mat*FKV_B + off, src[mat] + r*HD + c*8);
            }
    }
    CP_COMMIT();
    // pb slice for kt=0: rel = 0*64 - qt*128 + 1023 - 127 + i,  i in [0,192)
    if (tid < 192) pb_s[tid] = g_pb[h*2048 - qt*128 + 896 + tid];
    CP_WAIT(0);
    __syncthreads();

    // ---- Q fragments (register resident) ----
    uint32_t aQh[4][4], aQl[4][4];
    {
        const int ar = lane & 15, ac8 = lane >> 4;
        #pragma unroll
        for (int k16 = 0; k16 < 4; k16++) {
            uint32_t off = SWZ((uint32_t)((w*16 + ar)*128 + k16*32 + ac8*16));
            ldmx4(aQh[k16], sb + off);
            ldmx4(aQl[k16], sb + FQ_B + off);
        }
    }

    const int tg = lane >> 2, tig = lane & 3;
    const int qloc0 = w*16 + tg, qloc1 = qloc0 + 8;
    const float gate0 = g_gate[bh*T_ + qt*128 + qloc0];
    const float gate1 = g_gate[bh*T_ + qt*128 + qloc1];

    float m0 = -1e30f, m1 = -1e30f, l0 = 0.f, l1 = 0.f;
    float oacc[8][4];
    #pragma unroll
    for (int dt = 0; dt < 8; dt++)
        #pragma unroll
        for (int r = 0; r < 4; r++) oacc[dt][r] = 0.f;

    const int kb_row = (lane & 7) | ((lane & 16) >> 1);
    const int kb_c16 = (lane >> 3) & 1;
    const int v_row  = lane & 15;
    const int v_c16  = lane >> 4;

    for (int kt = 0; kt < 16; kt++) {
        const int s = kt & 1;
        // prefetch next KV stage + pb slice
        if (kt + 1 < 16) {
            const size_t koff = bhoff + (size_t)(kt+1)*64*HD;
            const __nv_bfloat16* src[4] = { g_kh + koff, g_kl + koff,
                                            g_vh + koff, g_vl + koff };
            uint32_t sdst = sb + F_SM_KV + (s^1)*F_STG_B;
            #pragma unroll
            for (int mat = 0; mat < 4; mat++)
                #pragma unroll
                for (int i = 0; i < 2; i++) {
                    int idx = tid + i * 256;
                    int r = idx >> 3, c = idx & 7;
                    uint32_t off = SWZ((uint32_t)(r*128 + c*16));
                    cpasync16(sdst + mat*FKV_B + off, src[mat] + r*HD + c*8);
                }
            CP_COMMIT();
            if (tid < 192)
                pb_s[(s^1)*192 + tid] = g_pb[h*2048 + (kt+1)*64 - qt*128 + 896 + tid];
        }

        // ---- S = Q K^T (3-term), 128q x 64k ----
        const uint32_t kbh = sb + F_SM_KV + s*F_STG_B;
        const uint32_t kbl = kbh + FKV_B;
        float sacc[8][4];
        #pragma unroll
        for (int j = 0; j < 8; j++)
            #pragma unroll
            for (int r = 0; r < 4; r++) sacc[j][r] = 0.f;

        #pragma unroll
        for (int k16 = 0; k16 < 4; k16++) {
            #pragma unroll
            for (int np = 0; np < 4; np++) {
                uint32_t off = SWZ((uint32_t)((np*16 + kb_row)*128 + k16*32 + kb_c16*16));
                uint32_t bkh[4], bkl[4];
                ldmx4(bkh, kbh + off);
                ldmx4(bkl, kbl + off);
                mma16816(sacc[2*np],   aQh[k16], bkh);
                mma16816(sacc[2*np],   aQh[k16], bkl);
                mma16816(sacc[2*np],   aQl[k16], bkh);
                mma16816(sacc[2*np+1], aQh[k16], bkh+2);
                mma16816(sacc[2*np+1], aQh[k16], bkl+2);
                mma16816(sacc[2*np+1], aQl[k16], bkh+2);
            }
        }

        // ---- bias + online softmax ----
        const float* pbc = pb_s + s*192;
        float mx0 = -1e30f, mx1 = -1e30f;
        #pragma unroll
        for (int j = 0; j < 8; j++) {
            int kl0 = j*8 + 2*tig;
            sacc[j][0] += gate0 * pbc[kl0     - qloc0 + 127];
            sacc[j][1] += gate0 * pbc[kl0 + 1 - qloc0 + 127];
            sacc[j][2] += gate1 * pbc[kl0     - qloc1 + 127];
            sacc[j][3] += gate1 * pbc[kl0 + 1 - qloc1 + 127];
            mx0 = fmaxf(mx0, fmaxf(sacc[j][0], sacc[j][1]));
            mx1 = fmaxf(mx1, fmaxf(sacc[j][2], sacc[j][3]));
        }
        mx0 = fmaxf(mx0, __shfl_xor_sync(0xffffffffu, mx0, 1));
        mx0 = fmaxf(mx0, __shfl_xor_sync(0xffffffffu, mx0, 2));
        mx1 = fmaxf(mx1, __shfl_xor_sync(0xffffffffu, mx1, 1));
        mx1 = fmaxf(mx1, __shfl_xor_sync(0xffffffffu, mx1, 2));

        float nm0 = fmaxf(m0, mx0), nm1 = fmaxf(m1, mx1);
        float sc0 = __expf(m0 - nm0), sc1 = __expf(m1 - nm1);
        m0 = nm0; m1 = nm1;

        float rs0 = 0.f, rs1 = 0.f;
        #pragma unroll
        for (int j = 0; j < 8; j++) {
            sacc[j][0] = __expf(sacc[j][0] - m0);
            sacc[j][1] = __expf(sacc[j][1] - m0);
            sacc[j][2] = __expf(sacc[j][2] - m1);
            sacc[j][3] = __expf(sacc[j][3] - m1);
            rs0 += sacc[j][0] + sacc[j][1];
            rs1 += sacc[j][2] + sacc[j][3];
        }
        rs0 += __shfl_xor_sync(0xffffffffu, rs0, 1);
        rs0 += __shfl_xor_sync(0xffffffffu, rs0, 2);
        rs1 += __shfl_xor_sync(0xffffffffu, rs1, 1);
        rs1 += __shfl_xor_sync(0xffffffffu, rs1, 2);
        l0 = l0 * sc0 + rs0;
        l1 = l1 * sc1 + rs1;

        #pragma unroll
        for (int dt = 0; dt < 8; dt++) {
            oacc[dt][0] *= sc0; oacc[dt][1] *= sc0;
            oacc[dt][2] *= sc1; oacc[dt][3] *= sc1;
        }

        // ---- O += P V (3-term), 64k x 64d ----
        const uint32_t vbh = kbh + 2*FKV_B;
        const uint32_t vbl = vbh + FKV_B;
        #pragma unroll
        for (int kk = 0; kk < 4; kk++) {
            uint32_t ph[4], pl[4];
            split2(sacc[2*kk][0],   sacc[2*kk][1],   ph[0], pl[0]);
            split2(sacc[2*kk][2],   sacc[2*kk][3],   ph[1], pl[1]);
            split2(sacc[2*kk+1][0], sacc[2*kk+1][1], ph[2], pl[2]);
            split2(sacc[2*kk+1][2], sacc[2*kk+1][3], ph[3], pl[3]);
            #pragma unroll
            for (int dt = 0; dt < 4; dt++) {
                uint32_t off = SWZ((uint32_t)((kk*16 + v_row)*128 + dt*32 + v_c16*16));
                uint32_t bvh[4], bvl[4];
                ldmx4t(bvh, vbh + off);
                ldmx4t(bvl, vbl + off);
                mma16816(oacc[2*dt],   ph, bvh);
                mma16816(oacc[2*dt],   ph, bvl);
                mma16816(oacc[2*dt],   pl, bvh);
                mma16816(oacc[2*dt+1], ph, bvh+2);
                mma16816(oacc[2*dt+1], ph, bvl+2);
                mma16816(oacc[2*dt+1], pl, bvh+2);
            }
        }

        if (kt + 1 < 16) {
            CP_WAIT(0);
            __syncthreads();
        }
    }

    // ---- epilogue ----
    float il0 = 1.f / l0, il1 = 1.f / l1;
    size_t row0 = (size_t)(b*T_ + qt*128 + qloc0) * D_ + h*HD;
    size_t row1 = (size_t)(b*T_ + qt*128 + qloc1) * D_ + h*HD;
    #pragma unroll
    for (int dt = 0; dt < 8; dt++) {
        int d = dt*8 + 2*tig;
        uint32_t hw, lw;
        split2(oacc[dt][0]*il0, oacc[dt][1]*il0, hw, lw);
        *(uint32_t*)(outh + row0 + d) = hw;
        *(uint32_t*)(outl + row0 + d) = lw;
        split2(oacc[dt][2]*il1, oacc[dt][3]*il1, hw, lw);
        *(uint32_t*)(outh + row1 + d) = hw;
        *(uint32_t*)(outl + row1 + d) = lw;
    }
}

// ---------------------------------------------------------------------------
extern "C" void kernel_launch(void* const* d_in, const int* in_sizes, int n_in,
                              void* d_out, int out_size)
{
    const float* hs    = (const float*)d_in[0];
    const float* q_w   = (const float*)d_in[1];
    const float* q_b   = (const float*)d_in[2];
    const float* k_w   = (const float*)d_in[3];
    const float* k_b   = (const float*)d_in[4];
    const float* v_w   = (const float*)d_in[5];
    const float* v_b   = (const float*)d_in[6];
    const float* out_w = (const float*)d_in[7];
    const float* out_b = (const float*)d_in[8];
    const float* rel   = (const float*)d_in[9];
    const float* gc    = (const float*)d_in[10];
    const float* gw    = (const float*)d_in[11];
    const float* gb    = (const float*)d_in[12];

    __nv_bfloat16 *ahi, *alo, *whi, *wlo;
    cudaGetSymbolAddress((void**)&ahi, g_a_hi);
    cudaGetSymbolAddress((void**)&alo, g_a_lo);
    cudaGetSymbolAddress((void**)&whi, g_w_hi);
    cudaGetSymbolAddress((void**)&wlo, g_w_lo);

    cudaFuncSetAttribute(qkv_mma_kernel,
                         cudaFuncAttributeMaxDynamicSharedMemorySize, SMEMT);
    cudaFuncSetAttribute(out_mma_kernel,
                         cudaFuncAttributeMaxDynamicSharedMemorySize, SMEMT);
    cudaFuncSetAttribute(flash_kernel,
                         cudaFuncAttributeMaxDynamicSharedMemorySize, F_SMEMT);

    pb_kernel<<<8, 256>>>(rel);
    gate_kernel<<<(BH*T_)/256, 256>>>(hs, gw, gb, gc);

    const size_t WSZ = (size_t)D_*D_;
    split_kernel<<<(M_*D_/4 + 255)/256, 256>>>(hs, ahi, alo, M_*D_/4);
    splitw_kernel<<<dim3(WSZ/4/256, 4), 256>>>(q_w, k_w, v_w, out_w, whi, wlo);

    // Merged Q/K/V projection: one launch, 768 CTAs
    qkv_mma_kernel<<<dim3(24, 32), 256, SMEMT>>>(ahi, alo, q_b, k_b, v_b);

    // Fused attention: writes ctx directly as split activations (reuses ahi/alo)
    flash_kernel<<<dim3(8, BH), 256, F_SMEMT>>>(ahi, alo);

    out_mma_kernel<<<dim3(8, 32), 256, SMEMT>>>(ahi, alo, out_b, (float*)d_out);
}

// round 11
// speedup vs baseline: 1.3519x; 1.3519x over previous
#include <cuda_runtime.h>
#include <cuda_fp16.h>
#include <math.h>
#include <stdint.h>

// Problem constants
#define B_  4
#define T_  1024
#define D_  1024
#define H_  16
#define HD  64
#define BH  (B_*H_)     // 64
#define M_  (B_*T_)     // 4096

// Scratch (static device globals — no allocation)
__device__ float g_gate[BH*T_];               // [bh][t]
__device__ float g_pb[H_*2048];               // [h][rel+1023]

// fp16 split buffers
__device__ __half g_a_hi[(size_t)M_*D_];      // activations hi (hs, later ctx)
__device__ __half g_a_lo[(size_t)M_*D_];      // activations lo
__device__ __half g_w_hi[(size_t)4*D_*D_];    // 4 weight matrices, hi only
// q/k/v in [bh][t][d]
__device__ __half g_qh[(size_t)BH*T_*HD];     // Q hi only
__device__ __half g_kh[(size_t)BH*T_*HD];     // K hi
__device__ __half g_kl[(size_t)BH*T_*HD];     // K lo
__device__ __half g_vh[(size_t)BH*T_*HD];     // V hi only

// ---------------------------------------------------------------------------
// PTX helpers
// ---------------------------------------------------------------------------
__device__ __forceinline__ uint32_t smem_u32(const void* p) {
    uint32_t a;
    asm("{ .reg .u64 t; cvta.to.shared.u64 t, %1; cvt.u32.u64 %0, t; }" : "=r"(a) : "l"(p));
    return a;
}
__device__ __forceinline__ void ldmx4(uint32_t* r, uint32_t addr) {
    asm volatile("ldmatrix.sync.aligned.m8n8.x4.shared.b16 {%0,%1,%2,%3}, [%4];"
        : "=r"(r[0]), "=r"(r[1]), "=r"(r[2]), "=r"(r[3]) : "r"(addr));
}
__device__ __forceinline__ void ldmx4t(uint32_t* r, uint32_t addr) {
    asm volatile("ldmatrix.sync.aligned.m8n8.x4.trans.shared.b16 {%0,%1,%2,%3}, [%4];"
        : "=r"(r[0]), "=r"(r[1]), "=r"(r[2]), "=r"(r[3]) : "r"(addr));
}
__device__ __forceinline__ void mma16816(float* c, const uint32_t* a, const uint32_t* b) {
    asm volatile("mma.sync.aligned.m16n8k16.row.col.f32.f16.f16.f32 "
        "{%0,%1,%2,%3}, {%4,%5,%6,%7}, {%8,%9}, {%0,%1,%2,%3};"
        : "+f"(c[0]), "+f"(c[1]), "+f"(c[2]), "+f"(c[3])
        : "r"(a[0]), "r"(a[1]), "r"(a[2]), "r"(a[3]), "r"(b[0]), "r"(b[1]));
}
__device__ __forceinline__ void cpasync16(uint32_t dst, const void* src) {
    asm volatile("cp.async.cg.shared.global [%0], [%1], 16;" :: "r"(dst), "l"(src));
}
#define CP_COMMIT()  asm volatile("cp.async.commit_group;" ::: "memory")
#define CP_WAIT(n)   asm volatile("cp.async.wait_group %0;" :: "n"(n) : "memory")
#define SWZ(o) ((o) ^ (((o) >> 3) & 0x70))

// split pair of floats into fp16x2 hi and lo words
__device__ __forceinline__ void split2h(float x, float y, uint32_t& h, uint32_t& l) {
    __half2 hh = __floats2half2_rn(x, y);
    float hx = __low2float(hh), hy = __high2float(hh);
    __half2 ll = __floats2half2_rn(x - hx, y - hy);
    h = *(uint32_t*)&hh;
    l = *(uint32_t*)&ll;
}

// ---------------------------------------------------------------------------
// Split fp32 -> fp16 hi/lo (activations)
// ---------------------------------------------------------------------------
__global__ void split_kernel(const float* __restrict__ x,
                             __half* __restrict__ hi,
                             __half* __restrict__ lo, int n4)
{
    int i = blockIdx.x * blockDim.x + threadIdx.x;
    if (i >= n4) return;
    float4 v = ((const float4*)x)[i];
    uint32_t h0, l0, h1, l1;
    split2h(v.x, v.y, h0, l0);
    split2h(v.z, v.w, h1, l1);
    ((uint32_t*)hi)[2*i+0] = h0; ((uint32_t*)hi)[2*i+1] = h1;
    ((uint32_t*)lo)[2*i+0] = l0; ((uint32_t*)lo)[2*i+1] = l1;
}

// Fused convert of the 4 weight matrices to fp16 hi (no lo needed)
__global__ void splitw_kernel(const float* __restrict__ w0,
                              const float* __restrict__ w1,
                              const float* __restrict__ w2,
                              const float* __restrict__ w3,
                              __half* __restrict__ hi)
{
    const int mat = blockIdx.y;
    const float* x = (mat == 0) ? w0 : (mat == 1) ? w1 : (mat == 2) ? w2 : w3;
    const size_t base = (size_t)mat * D_ * D_;
    int i = blockIdx.x * blockDim.x + threadIdx.x;     // 0 .. D*D/4
    float4 v = ((const float4*)x)[i];
    __half2 h0 = __floats2half2_rn(v.x, v.y);
    __half2 h1 = __floats2half2_rn(v.z, v.w);
    ((uint32_t*)(hi + base))[2*i+0] = *(uint32_t*)&h0;
    ((uint32_t*)(hi + base))[2*i+1] = *(uint32_t*)&h1;
}

// ---------------------------------------------------------------------------
// mma.sync projection GEMM core: C = (Ah + Al) @ Wh^T  (2-term fp16)
// Stage = Ah, Al, Wh tiles (3 matrices).
// ---------------------------------------------------------------------------
#define SST    40
#define MAT_B  (128*SST*2)        // 10240
#define STG_B  (3*MAT_B)          // 30720
#define SMEMT  (2*STG_B)          // 61440

__device__ __forceinline__ void proj_tile(
    const __half* __restrict__ Ahi,
    const __half* __restrict__ Alo,
    const __half* __restrict__ Whi,
    const float* __restrict__ bias,
    float* __restrict__ outf,
    __half* __restrict__ outh,
    __half* __restrict__ outl,
    float scale, int remap, int m0, int n0, char* sm)
{
    const uint32_t sb = smem_u32(sm);
    const int tid = threadIdx.x;
    const int lane = tid & 31, wid = tid >> 5;
    const int wm = (wid >> 2) * 64, wn = (wid & 3) * 32;

    const __half* gsrc[3];
    gsrc[0] = Ahi + (size_t)m0 * D_;
    gsrc[1] = Alo + (size_t)m0 * D_;
    gsrc[2] = Whi + (size_t)n0 * D_;

    auto issue = [&](int kt, int s) {
        uint32_t sdst = sb + s * STG_B;
        #pragma unroll
        for (int mat = 0; mat < 3; mat++) {
            const __half* g = gsrc[mat] + kt * 32;
            #pragma unroll
            for (int i = 0; i < 2; i++) {
                int idx = tid + i * 256;
                int r = idx >> 2, c = idx & 3;
                cpasync16(sdst + mat*MAT_B + (uint32_t)(r*SST + c*8)*2,
                          g + (size_t)r * D_ + c * 8);
            }
        }
        CP_COMMIT();
    };

    float acc[4][4][4];
    #pragma unroll
    for (int mt = 0; mt < 4; mt++)
        #pragma unroll
        for (int nt = 0; nt < 4; nt++)
            #pragma unroll
            for (int r = 0; r < 4; r++) acc[mt][nt][r] = 0.f;

    issue(0, 0);

    const int ar   = lane & 15;
    const int ac8  = lane >> 4;
    const int brow = (lane & 7) | ((lane & 16) >> 1);
    const int bc8  = (lane >> 3) & 1;

    for (int kt = 0; kt < 32; kt++) {
        const int s = kt & 1;
        if (kt + 1 < 32) { issue(kt + 1, s ^ 1); CP_WAIT(1); }
        else             { CP_WAIT(0); }
        __syncthreads();

        const uint32_t base = sb + s * STG_B;
        #pragma unroll
        for (int k16 = 0; k16 < 2; k16++) {
            uint32_t aH[4][4], aL[4][4];
            #pragma unroll
            for (int mt = 0; mt < 4; mt++) {
                uint32_t off = (uint32_t)((wm + mt*16 + ar)*SST + k16*16 + ac8*8) * 2;
                ldmx4(aH[mt], base + 0*MAT_B + off);
                ldmx4(aL[mt], base + 1*MAT_B + off);
            }
            #pragma unroll
            for (int np = 0; np < 2; np++) {
                uint32_t bh4[4];
                uint32_t off = (uint32_t)((wn + np*16 + brow)*SST + k16*16 + bc8*8) * 2;
                ldmx4(bh4, base + 2*MAT_B + off);
                #pragma unroll
                for (int mt = 0; mt < 4; mt++) {
                    mma16816(acc[mt][2*np],   aH[mt], bh4);
                    mma16816(acc[mt][2*np],   aL[mt], bh4);
                    mma16816(acc[mt][2*np+1], aH[mt], bh4+2);
                    mma16816(acc[mt][2*np+1], aL[mt], bh4+2);
                }
            }
        }
        __syncthreads();
    }

    const int tg = lane >> 2, tig = lane & 3;
    #pragma unroll
    for (int mt = 0; mt < 4; mt++)
        #pragma unroll
        for (int i2 = 0; i2 < 2; i2++) {
            int m = m0 + wm + mt*16 + tg + i2*8;
            #pragma unroll
            for (int nt = 0; nt < 4; nt++) {
                int n = n0 + wn + nt*8 + tig*2;
                float v0 = (acc[mt][nt][i2*2+0] + bias[n])   * scale;
                float v1 = (acc[mt][nt][i2*2+1] + bias[n+1]) * scale;
                if (remap) {
                    int b = m >> 10, t = m & 1023;
                    int h = n >> 6,  d = n & 63;
                    size_t off = (((size_t)(b*H_ + h)*T_ + t))*HD + d;
                    uint32_t hw, lw;
                    split2h(v0, v1, hw, lw);
                    *(uint32_t*)(outh + off) = hw;
                    if (outl) *(uint32_t*)(outl + off) = lw;
                } else {
                    *(float2*)(outf + (size_t)m*D_ + n) = make_float2(v0, v1);
                }
            }
        }
}

// Merged Q/K/V projection: grid.x = 24 (mat = x>>3, n-block = x&7), grid.y = 32.
__global__ __launch_bounds__(256, 2)
void qkv_mma_kernel(const __half* __restrict__ Ahi,
                    const __half* __restrict__ Alo,
                    const float* __restrict__ q_b,
                    const float* __restrict__ k_b,
                    const float* __restrict__ v_b)
{
    extern __shared__ char sm[];
    const int mat = blockIdx.x >> 3;
    const int n0  = (blockIdx.x & 7) * 128;
    const int m0  = blockIdx.y * 128;
    const size_t WSZ = (size_t)D_*D_;
    const float* bias = (mat == 0) ? q_b : (mat == 1) ? k_b : v_b;
    const float scale = (mat == 0) ? 0.125f : 1.0f;
    __half* outh = (mat == 0) ? g_qh : (mat == 1) ? g_kh : g_vh;
    __half* outl = (mat == 1) ? g_kl : (__half*)nullptr;  // only K keeps lo

    proj_tile(Ahi, Alo, g_w_hi + mat*WSZ, bias,
              nullptr, outh, outl, scale, 1, m0, n0, sm);
}

// Output projection (fp32 out)
__global__ __launch_bounds__(256, 2)
void out_mma_kernel(const __half* __restrict__ Ahi,
                    const __half* __restrict__ Alo,
                    const float* __restrict__ bias,
                    float* __restrict__ out)
{
    extern __shared__ char sm[];
    const size_t WSZ = (size_t)D_*D_;
    proj_tile(Ahi, Alo, g_w_hi + 3*WSZ, bias,
              out, nullptr, nullptr, 1.0f, 0,
              blockIdx.y * 128, blockIdx.x * 128, sm);
}

// ---------------------------------------------------------------------------
// Position-bias LUT
// ---------------------------------------------------------------------------
__global__ void pb_kernel(const float* __restrict__ rel_embed)
{
    int d = blockIdx.x * blockDim.x + threadIdx.x;
    if (d >= 2047) return;
    int rel = d - 1023;
    int rb  = (rel > 0) ? 160 : 0;
    int rp  = rel < 0 ? -rel : rel;
    int bucket;
    if (rp < 80) {
        bucket = rb + rp;
    } else {
        float t = logf((float)rp / 80.0f) / logf(10.0f);
        t = t * 80.0f;
        float v = 80.0f + t;
        int bi = (int)v;
        bucket = rb + (bi < 159 ? bi : 159);
    }
    #pragma unroll
    for (int h = 0; h < H_; h++)
        g_pb[h*2048 + d] = rel_embed[bucket*H_ + h];
}

// ---------------------------------------------------------------------------
// Gate
// ---------------------------------------------------------------------------
__global__ void gate_kernel(const float* __restrict__ hs,
                            const float* __restrict__ gw,
                            const float* __restrict__ gb,
                            const float* __restrict__ gc)
{
    int idx = blockIdx.x * blockDim.x + threadIdx.x;
    if (idx >= BH*T_) return;
    int t  = idx & (T_-1);
    int bh = idx >> 10;
    int h  = bh & (H_-1);
    int b  = bh >> 4;

    const float4* x = (const float4*)(hs + ((size_t)(b*T_+t))*D_ + h*HD);
    float p[8];
    #pragma unroll
    for (int e = 0; e < 8; e++) p[e] = 0.f;
    #pragma unroll
    for (int i = 0; i < 16; i++) {
        float4 xv = x[i];
        #pragma unroll
        for (int e = 0; e < 8; e++) {
            const float* w = gw + e*HD + i*4;
            p[e] += xv.x*w[0] + xv.y*w[1] + xv.z*w[2] + xv.w*w[3];
        }
    }
    float pa = p[0]+p[1]+p[2]+p[3] + gb[0]+gb[1]+gb[2]+gb[3];
    float pbv= p[4]+p[5]+p[6]+p[7] + gb[4]+gb[5]+gb[6]+gb[7];
    float ga  = 1.f/(1.f + expf(-pa));
    float gbs = 1.f/(1.f + expf(-pbv));
    g_gate[idx] = ga * (gbs * gc[h] - 1.f) + 2.f;
}

// ---------------------------------------------------------------------------
// Fused flash attention — fp16 2-term, 64-row KV tiles, 2 CTAs/SM.
// QK: Qh·Kh + Qh·Kl.  PV: Ph·Vh + Pl·Vh.
// ---------------------------------------------------------------------------
#define FQ_B      16384                 // 128 x 64 fp16 (Q hi)
#define FKV_B     8192                  // 64 x 64 fp16 (one matrix)
#define F_STG_B   (3*FKV_B)             // Kh, Kl, Vh = 24 KB
#define F_SM_KV   FQ_B
#define F_SM_PB   (F_SM_KV + 2*F_STG_B) // 65536
#define F_SMEMT   (F_SM_PB + 2*192*4)   // 67072

__global__ __launch_bounds__(256, 2)
void flash_kernel(__half* __restrict__ outh,
                  __half* __restrict__ outl)
{
    extern __shared__ char sm[];
    const uint32_t sb = smem_u32(sm);
    float* pb_s = (float*)(sm + F_SM_PB);

    const int tid  = threadIdx.x;
    const int lane = tid & 31, w = tid >> 5;
    const int qt = blockIdx.x, bh = blockIdx.y;
    const int b = bh >> 4, h = bh & 15;
    const size_t bhoff = (size_t)bh * T_ * HD;

    const __half* gQh = g_qh + bhoff + (size_t)qt*128*HD;

    // ---- prologue: Q + KV stage 0 + pb slice 0 ----
    #pragma unroll
    for (int i = 0; i < 4; i++) {
        int idx = tid + i * 256;
        int r = idx >> 3, c = idx & 7;
        uint32_t off = SWZ((uint32_t)(r*128 + c*16));
        cpasync16(sb + off, gQh + r*HD + c*8);
    }
    {
        const __half* src[3] = { g_kh + bhoff, g_kl + bhoff, g_vh + bhoff };
        #pragma unroll
        for (int mat = 0; mat < 3; mat++)
            #pragma unroll
            for (int i = 0; i < 2; i++) {
                int idx = tid + i * 256;
                int r = idx >> 3, c = idx & 7;
                uint32_t off = SWZ((uint32_t)(r*128 + c*16));
                cpasync16(sb + F_SM_KV + mat*FKV_B + off, src[mat] + r*HD + c*8);
            }
    }
    CP_COMMIT();
    if (tid < 192) pb_s[tid] = g_pb[h*2048 - qt*128 + 896 + tid];
    CP_WAIT(0);
    __syncthreads();

    // ---- Q fragments (register resident, hi only) ----
    uint32_t aQh[4][4];
    {
        const int ar = lane & 15, ac8 = lane >> 4;
        #pragma unroll
        for (int k16 = 0; k16 < 4; k16++) {
            uint32_t off = SWZ((uint32_t)((w*16 + ar)*128 + k16*32 + ac8*16));
            ldmx4(aQh[k16], sb + off);
        }
    }

    const int tg = lane >> 2, tig = lane & 3;
    const int qloc0 = w*16 + tg, qloc1 = qloc0 + 8;
    const float gate0 = g_gate[bh*T_ + qt*128 + qloc0];
    const float gate1 = g_gate[bh*T_ + qt*128 + qloc1];

    float m0 = -1e30f, m1 = -1e30f, l0 = 0.f, l1 = 0.f;
    float oacc[8][4];
    #pragma unroll
    for (int dt = 0; dt < 8; dt++)
        #pragma unroll
        for (int r = 0; r < 4; r++) oacc[dt][r] = 0.f;

    const int kb_row = (lane & 7) | ((lane & 16) >> 1);
    const int kb_c16 = (lane >> 3) & 1;
    const int v_row  = lane & 15;
    const int v_c16  = lane >> 4;

    for (int kt = 0; kt < 16; kt++) {
        const int s = kt & 1;
        // prefetch next KV stage + pb slice
        if (kt + 1 < 16) {
            const size_t koff = bhoff + (size_t)(kt+1)*64*HD;
            const __half* src[3] = { g_kh + koff, g_kl + koff, g_vh + koff };
            uint32_t sdst = sb + F_SM_KV + (s^1)*F_STG_B;
            #pragma unroll
            for (int mat = 0; mat < 3; mat++)
                #pragma unroll
                for (int i = 0; i < 2; i++) {
                    int idx = tid + i * 256;
                    int r = idx >> 3, c = idx & 7;
                    uint32_t off = SWZ((uint32_t)(r*128 + c*16));
                    cpasync16(sdst + mat*FKV_B + off, src[mat] + r*HD + c*8);
                }
            CP_COMMIT();
            if (tid < 192)
                pb_s[(s^1)*192 + tid] = g_pb[h*2048 + (kt+1)*64 - qt*128 + 896 + tid];
        }

        // ---- S = Qh·(Kh + Kl), 128q x 64k ----
        const uint32_t kbh = sb + F_SM_KV + s*F_STG_B;
        const uint32_t kbl = kbh + FKV_B;
        float sacc[8][4];
        #pragma unroll
        for (int j = 0; j < 8; j++)
            #pragma unroll
            for (int r = 0; r < 4; r++) sacc[j][r] = 0.f;

        #pragma unroll
        for (int k16 = 0; k16 < 4; k16++) {
            #pragma unroll
            for (int np = 0; np < 4; np++) {
                uint32_t off = SWZ((uint32_t)((np*16 + kb_row)*128 + k16*32 + kb_c16*16));
                uint32_t bkh[4], bkl[4];
                ldmx4(bkh, kbh + off);
                ldmx4(bkl, kbl + off);
                mma16816(sacc[2*np],   aQh[k16], bkh);
                mma16816(sacc[2*np],   aQh[k16], bkl);
                mma16816(sacc[2*np+1], aQh[k16], bkh+2);
                mma16816(sacc[2*np+1], aQh[k16], bkl+2);
            }
        }

        // ---- bias + online softmax ----
        const float* pbc = pb_s + s*192;
        float mx0 = -1e30f, mx1 = -1e30f;
        #pragma unroll
        for (int j = 0; j < 8; j++) {
            int kl0 = j*8 + 2*tig;
            sacc[j][0] += gate0 * pbc[kl0     - qloc0 + 127];
            sacc[j][1] += gate0 * pbc[kl0 + 1 - qloc0 + 127];
            sacc[j][2] += gate1 * pbc[kl0     - qloc1 + 127];
            sacc[j][3] += gate1 * pbc[kl0 + 1 - qloc1 + 127];
            mx0 = fmaxf(mx0, fmaxf(sacc[j][0], sacc[j][1]));
            mx1 = fmaxf(mx1, fmaxf(sacc[j][2], sacc[j][3]));
        }
        mx0 = fmaxf(mx0, __shfl_xor_sync(0xffffffffu, mx0, 1));
        mx0 = fmaxf(mx0, __shfl_xor_sync(0xffffffffu, mx0, 2));
        mx1 = fmaxf(mx1, __shfl_xor_sync(0xffffffffu, mx1, 1));
        mx1 = fmaxf(mx1, __shfl_xor_sync(0xffffffffu, mx1, 2));

        float nm0 = fmaxf(m0, mx0), nm1 = fmaxf(m1, mx1);
        float sc0 = __expf(m0 - nm0), sc1 = __expf(m1 - nm1);
        m0 = nm0; m1 = nm1;

        float rs0 = 0.f, rs1 = 0.f;
        #pragma unroll
        for (int j = 0; j < 8; j++) {
            sacc[j][0] = __expf(sacc[j][0] - m0);
            sacc[j][1] = __expf(sacc[j][1] - m0);
            sacc[j][2] = __expf(sacc[j][2] - m1);
            sacc[j][3] = __expf(sacc[j][3] - m1);
            rs0 += sacc[j][0] + sacc[j][1];
            rs1 += sacc[j][2] + sacc[j][3];
        }
        rs0 += __shfl_xor_sync(0xffffffffu, rs0, 1);
        rs0 += __shfl_xor_sync(0xffffffffu, rs0, 2);
        rs1 += __shfl_xor_sync(0xffffffffu, rs1, 1);
        rs1 += __shfl_xor_sync(0xffffffffu, rs1, 2);
        l0 = l0 * sc0 + rs0;
        l1 = l1 * sc1 + rs1;

        #pragma unroll
        for (int dt = 0; dt < 8; dt++) {
            oacc[dt][0] *= sc0; oacc[dt][1] *= sc0;
            oacc[dt][2] *= sc1; oacc[dt][3] *= sc1;
        }

        // ---- O += (Ph + Pl)·Vh, 64k x 64d ----
        const uint32_t vbh = kbh + 2*FKV_B;
        #pragma unroll
        for (int kk = 0; kk < 4; kk++) {
            uint32_t ph[4], pl[4];
            split2h(sacc[2*kk][0],   sacc[2*kk][1],   ph[0], pl[0]);
            split2h(sacc[2*kk][2],   sacc[2*kk][3],   ph[1], pl[1]);
            split2h(sacc[2*kk+1][0], sacc[2*kk+1][1], ph[2], pl[2]);
            split2h(sacc[2*kk+1][2], sacc[2*kk+1][3], ph[3], pl[3]);
            #pragma unroll
            for (int dt = 0; dt < 4; dt++) {
                uint32_t off = SWZ((uint32_t)((kk*16 + v_row)*128 + dt*32 + v_c16*16));
                uint32_t bvh[4];
                ldmx4t(bvh, vbh + off);
                mma16816(oacc[2*dt],   ph, bvh);
                mma16816(oacc[2*dt],   pl, bvh);
                mma16816(oacc[2*dt+1], ph, bvh+2);
                mma16816(oacc[2*dt+1], pl, bvh+2);
            }
        }

        if (kt + 1 < 16) {
            CP_WAIT(0);
            __syncthreads();
        }
    }

    // ---- epilogue: O /= l, write fp16 hi/lo into activation layout ----
    float il0 = 1.f / l0, il1 = 1.f / l1;
    size_t row0 = (size_t)(b*T_ + qt*128 + qloc0) * D_ + h*HD;
    size_t row1 = (size_t)(b*T_ + qt*128 + qloc1) * D_ + h*HD;
    #pragma unroll
    for (int dt = 0; dt < 8; dt++) {
        int d = dt*8 + 2*tig;
        uint32_t hw, lw;
        split2h(oacc[dt][0]*il0, oacc[dt][1]*il0, hw, lw);
        *(uint32_t*)(outh + row0 + d) = hw;
        *(uint32_t*)(outl + row0 + d) = lw;
        split2h(oacc[dt][2]*il1, oacc[dt][3]*il1, hw, lw);
        *(uint32_t*)(outh + row1 + d) = hw;
        *(uint32_t*)(outl + row1 + d) = lw;
    }
}

// ---------------------------------------------------------------------------
extern "C" void kernel_launch(void* const* d_in, const int* in_sizes, int n_in,
                              void* d_out, int out_size)
{
    const float* hs    = (const float*)d_in[0];
    const float* q_w   = (const float*)d_in[1];
    const float* q_b   = (const float*)d_in[2];
    const float* k_w   = (const float*)d_in[3];
    const float* k_b   = (const float*)d_in[4];
    const float* v_w   = (const float*)d_in[5];
    const float* v_b   = (const float*)d_in[6];
    const float* out_w = (const float*)d_in[7];
    const float* out_b = (const float*)d_in[8];
    const float* rel   = (const float*)d_in[9];
    const float* gc    = (const float*)d_in[10];
    const float* gw    = (const float*)d_in[11];
    const float* gb    = (const float*)d_in[12];

    __half *ahi, *alo, *whi;
    cudaGetSymbolAddress((void**)&ahi, g_a_hi);
    cudaGetSymbolAddress((void**)&alo, g_a_lo);
    cudaGetSymbolAddress((void**)&whi, g_w_hi);

    cudaFuncSetAttribute(qkv_mma_kernel,
                         cudaFuncAttributeMaxDynamicSharedMemorySize, SMEMT);
    cudaFuncSetAttribute(out_mma_kernel,
                         cudaFuncAttributeMaxDynamicSharedMemorySize, SMEMT);
    cudaFuncSetAttribute(flash_kernel,
                         cudaFuncAttributeMaxDynamicSharedMemorySize, F_SMEMT);

    pb_kernel<<<8, 256>>>(rel);
    gate_kernel<<<(BH*T_)/256, 256>>>(hs, gw, gb, gc);

    const size_t WSZ = (size_t)D_*D_;
    split_kernel<<<(M_*D_/4 + 255)/256, 256>>>(hs, ahi, alo, M_*D_/4);
    splitw_kernel<<<dim3(WSZ/4/256, 4), 256>>>(q_w, k_w, v_w, out_w, whi);

    // Merged Q/K/V projection: one launch, 768 CTAs
    qkv_mma_kernel<<<dim3(24, 32), 256, SMEMT>>>(ahi, alo, q_b, k_b, v_b);

    // Fused attention: writes ctx directly as split activations (reuses ahi/alo)
    flash_kernel<<<dim3(8, BH), 256, F_SMEMT>>>(ahi, alo);

    out_mma_kernel<<<dim3(8, 32), 256, SMEMT>>>(ahi, alo, out_b, (float*)d_out);
}

// round 12
// speedup vs baseline: 1.5549x; 1.1502x over previous
#include <cuda_runtime.h>
#include <cuda_fp16.h>
#include <math.h>
#include <stdint.h>

// Problem constants
#define B_  4
#define T_  1024
#define D_  1024
#define H_  16
#define HD  64
#define BH  (B_*H_)     // 64
#define M_  (B_*T_)     // 4096

// Scratch (static device globals — no allocation)
__device__ float g_gate[BH*T_];               // [bh][t]
__device__ float g_pb[H_*2048];               // [h][rel+1023]

// fp16 buffers
__device__ __half g_a_hi[(size_t)M_*D_];      // activations hi (hs, later ctx)
__device__ __half g_a_lo[(size_t)M_*D_];      // activations lo (hs only)
__device__ __half g_w_hi[(size_t)4*D_*D_];    // 4 weight matrices, hi only
// q/k/v in [bh][t][d], hi only
__device__ __half g_qh[(size_t)BH*T_*HD];
__device__ __half g_kh[(size_t)BH*T_*HD];
__device__ __half g_vh[(size_t)BH*T_*HD];

// ---------------------------------------------------------------------------
// PTX helpers
// ---------------------------------------------------------------------------
__device__ __forceinline__ uint32_t smem_u32(const void* p) {
    uint32_t a;
    asm("{ .reg .u64 t; cvta.to.shared.u64 t, %1; cvt.u32.u64 %0, t; }" : "=r"(a) : "l"(p));
    return a;
}
__device__ __forceinline__ void ldmx4(uint32_t* r, uint32_t addr) {
    asm volatile("ldmatrix.sync.aligned.m8n8.x4.shared.b16 {%0,%1,%2,%3}, [%4];"
        : "=r"(r[0]), "=r"(r[1]), "=r"(r[2]), "=r"(r[3]) : "r"(addr));
}
__device__ __forceinline__ void ldmx4t(uint32_t* r, uint32_t addr) {
    asm volatile("ldmatrix.sync.aligned.m8n8.x4.trans.shared.b16 {%0,%1,%2,%3}, [%4];"
        : "=r"(r[0]), "=r"(r[1]), "=r"(r[2]), "=r"(r[3]) : "r"(addr));
}
__device__ __forceinline__ void mma16816(float* c, const uint32_t* a, const uint32_t* b) {
    asm volatile("mma.sync.aligned.m16n8k16.row.col.f32.f16.f16.f32 "
        "{%0,%1,%2,%3}, {%4,%5,%6,%7}, {%8,%9}, {%0,%1,%2,%3};"
        : "+f"(c[0]), "+f"(c[1]), "+f"(c[2]), "+f"(c[3])
        : "r"(a[0]), "r"(a[1]), "r"(a[2]), "r"(a[3]), "r"(b[0]), "r"(b[1]));
}
__device__ __forceinline__ void cpasync16(uint32_t dst, const void* src) {
    asm volatile("cp.async.cg.shared.global [%0], [%1], 16;" :: "r"(dst), "l"(src));
}
#define CP_COMMIT()  asm volatile("cp.async.commit_group;" ::: "memory")
#define CP_WAIT(n)   asm volatile("cp.async.wait_group %0;" :: "n"(n) : "memory")
#define SWZ(o) ((o) ^ (((o) >> 3) & 0x70))

// split pair of floats into fp16x2 hi and lo words
__device__ __forceinline__ void split2h(float x, float y, uint32_t& h, uint32_t& l) {
    __half2 hh = __floats2half2_rn(x, y);
    float hx = __low2float(hh), hy = __high2float(hh);
    __half2 ll = __floats2half2_rn(x - hx, y - hy);
    h = *(uint32_t*)&hh;
    l = *(uint32_t*)&ll;
}

// ---------------------------------------------------------------------------
// Split fp32 -> fp16 hi/lo (activations)
// ---------------------------------------------------------------------------
__global__ void split_kernel(const float* __restrict__ x,
                             __half* __restrict__ hi,
                             __half* __restrict__ lo, int n4)
{
    int i = blockIdx.x * blockDim.x + threadIdx.x;
    if (i >= n4) return;
    float4 v = ((const float4*)x)[i];
    uint32_t h0, l0, h1, l1;
    split2h(v.x, v.y, h0, l0);
    split2h(v.z, v.w, h1, l1);
    ((uint32_t*)hi)[2*i+0] = h0; ((uint32_t*)hi)[2*i+1] = h1;
    ((uint32_t*)lo)[2*i+0] = l0; ((uint32_t*)lo)[2*i+1] = l1;
}

// Fused convert of the 4 weight matrices to fp16 hi
__global__ void splitw_kernel(const float* __restrict__ w0,
                              const float* __restrict__ w1,
                              const float* __restrict__ w2,
                              const float* __restrict__ w3,
                              __half* __restrict__ hi)
{
    const int mat = blockIdx.y;
    const float* x = (mat == 0) ? w0 : (mat == 1) ? w1 : (mat == 2) ? w2 : w3;
    const size_t base = (size_t)mat * D_ * D_;
    int i = blockIdx.x * blockDim.x + threadIdx.x;
    float4 v = ((const float4*)x)[i];
    __half2 h0 = __floats2half2_rn(v.x, v.y);
    __half2 h1 = __floats2half2_rn(v.z, v.w);
    ((uint32_t*)(hi + base))[2*i+0] = *(uint32_t*)&h0;
    ((uint32_t*)(hi + base))[2*i+1] = *(uint32_t*)&h1;
}

// ---------------------------------------------------------------------------
// mma.sync projection GEMM core. TWO=1: C = (Ah+Al)·Wh^T; TWO=0: C = Ah·Wh^T.
// Stage = Ah, (Al), Wh tiles.
// ---------------------------------------------------------------------------
#define SST    40
#define MAT_B  (128*SST*2)        // 10240
#define STG_B  (3*MAT_B)          // 30720 (slot 1 unused when TWO=0)
#define SMEMT  (2*STG_B)          // 61440

template<int TWO>
__device__ __forceinline__ void proj_tile(
    const __half* __restrict__ Ahi,
    const __half* __restrict__ Alo,
    const __half* __restrict__ Whi,
    const float* __restrict__ bias,
    float* __restrict__ outf,
    __half* __restrict__ outh,
    float scale, int remap, int m0, int n0, char* sm)
{
    const uint32_t sb = smem_u32(sm);
    const int tid = threadIdx.x;
    const int lane = tid & 31, wid = tid >> 5;
    const int wm = (wid >> 2) * 64, wn = (wid & 3) * 32;

    const __half* gsrc[3];
    gsrc[0] = Ahi + (size_t)m0 * D_;
    gsrc[1] = Alo + (size_t)m0 * D_;
    gsrc[2] = Whi + (size_t)n0 * D_;

    auto issue = [&](int kt, int s) {
        uint32_t sdst = sb + s * STG_B;
        #pragma unroll
        for (int mat = 0; mat < 3; mat++) {
            if (!TWO && mat == 1) continue;
            const __half* g = gsrc[mat] + kt * 32;
            #pragma unroll
            for (int i = 0; i < 2; i++) {
                int idx = tid + i * 256;
                int r = idx >> 2, c = idx & 3;
                cpasync16(sdst + mat*MAT_B + (uint32_t)(r*SST + c*8)*2,
                          g + (size_t)r * D_ + c * 8);
            }
        }
        CP_COMMIT();
    };

    float acc[4][4][4];
    #pragma unroll
    for (int mt = 0; mt < 4; mt++)
        #pragma unroll
        for (int nt = 0; nt < 4; nt++)
            #pragma unroll
            for (int r = 0; r < 4; r++) acc[mt][nt][r] = 0.f;

    issue(0, 0);

    const int ar   = lane & 15;
    const int ac8  = lane >> 4;
    const int brow = (lane & 7) | ((lane & 16) >> 1);
    const int bc8  = (lane >> 3) & 1;

    for (int kt = 0; kt < 32; kt++) {
        const int s = kt & 1;
        if (kt + 1 < 32) { issue(kt + 1, s ^ 1); CP_WAIT(1); }
        else             { CP_WAIT(0); }
        __syncthreads();

        const uint32_t base = sb + s * STG_B;
        #pragma unroll
        for (int k16 = 0; k16 < 2; k16++) {
            uint32_t aH[4][4], aL[4][4];
            #pragma unroll
            for (int mt = 0; mt < 4; mt++) {
                uint32_t off = (uint32_t)((wm + mt*16 + ar)*SST + k16*16 + ac8*8) * 2;
                ldmx4(aH[mt], base + 0*MAT_B + off);
                if (TWO) ldmx4(aL[mt], base + 1*MAT_B + off);
            }
            #pragma unroll
            for (int np = 0; np < 2; np++) {
                uint32_t bh4[4];
                uint32_t off = (uint32_t)((wn + np*16 + brow)*SST + k16*16 + bc8*8) * 2;
                ldmx4(bh4, base + 2*MAT_B + off);
                #pragma unroll
                for (int mt = 0; mt < 4; mt++) {
                    mma16816(acc[mt][2*np],   aH[mt], bh4);
                    if (TWO) mma16816(acc[mt][2*np], aL[mt], bh4);
                    mma16816(acc[mt][2*np+1], aH[mt], bh4+2);
                    if (TWO) mma16816(acc[mt][2*np+1], aL[mt], bh4+2);
                }
            }
        }
        __syncthreads();
    }

    const int tg = lane >> 2, tig = lane & 3;
    #pragma unroll
    for (int mt = 0; mt < 4; mt++)
        #pragma unroll
        for (int i2 = 0; i2 < 2; i2++) {
            int m = m0 + wm + mt*16 + tg + i2*8;
            #pragma unroll
            for (int nt = 0; nt < 4; nt++) {
                int n = n0 + wn + nt*8 + tig*2;
                float v0 = (acc[mt][nt][i2*2+0] + bias[n])   * scale;
                float v1 = (acc[mt][nt][i2*2+1] + bias[n+1]) * scale;
                if (remap) {
                    int b = m >> 10, t = m & 1023;
                    int h = n >> 6,  d = n & 63;
                    size_t off = (((size_t)(b*H_ + h)*T_ + t))*HD + d;
                    __half2 hv = __floats2half2_rn(v0, v1);
                    *(uint32_t*)(outh + off) = *(uint32_t*)&hv;
                } else {
                    *(float2*)(outf + (size_t)m*D_ + n) = make_float2(v0, v1);
                }
            }
        }
}

// Merged Q/K/V projection: grid.x = 24 (mat = x>>3, n-block = x&7), grid.y = 32.
__global__ __launch_bounds__(256, 2)
void qkv_mma_kernel(const __half* __restrict__ Ahi,
                    const __half* __restrict__ Alo,
                    const float* __restrict__ q_b,
                    const float* __restrict__ k_b,
                    const float* __restrict__ v_b)
{
    extern __shared__ char sm[];
    const int mat = blockIdx.x >> 3;
    const int n0  = (blockIdx.x & 7) * 128;
    const int m0  = blockIdx.y * 128;
    const size_t WSZ = (size_t)D_*D_;
    const float* bias = (mat == 0) ? q_b : (mat == 1) ? k_b : v_b;
    const float scale = (mat == 0) ? 0.125f : 1.0f;
    __half* outh = (mat == 0) ? g_qh : (mat == 1) ? g_kh : g_vh;

    proj_tile<1>(Ahi, Alo, g_w_hi + mat*WSZ, bias,
                 nullptr, outh, scale, 1, m0, n0, sm);
}

// Output projection (fp32 out, 1-term)
__global__ __launch_bounds__(256, 2)
void out_mma_kernel(const __half* __restrict__ Ahi,
                    const float* __restrict__ bias,
                    float* __restrict__ out)
{
    extern __shared__ char sm[];
    const size_t WSZ = (size_t)D_*D_;
    proj_tile<0>(Ahi, nullptr, g_w_hi + 3*WSZ, bias,
                 out, nullptr, 1.0f, 0,
                 blockIdx.y * 128, blockIdx.x * 128, sm);
}

// ---------------------------------------------------------------------------
// Position-bias LUT
// ---------------------------------------------------------------------------
__global__ void pb_kernel(const float* __restrict__ rel_embed)
{
    int d = blockIdx.x * blockDim.x + threadIdx.x;
    if (d >= 2047) return;
    int rel = d - 1023;
    int rb  = (rel > 0) ? 160 : 0;
    int rp  = rel < 0 ? -rel : rel;
    int bucket;
    if (rp < 80) {
        bucket = rb + rp;
    } else {
        float t = logf((float)rp / 80.0f) / logf(10.0f);
        t = t * 80.0f;
        float v = 80.0f + t;
        int bi = (int)v;
        bucket = rb + (bi < 159 ? bi : 159);
    }
    #pragma unroll
    for (int h = 0; h < H_; h++)
        g_pb[h*2048 + d] = rel_embed[bucket*H_ + h];
}

// ---------------------------------------------------------------------------
// Gate
// ---------------------------------------------------------------------------
__global__ void gate_kernel(const float* __restrict__ hs,
                            const float* __restrict__ gw,
                            const float* __restrict__ gb,
                            const float* __restrict__ gc)
{
    int idx = blockIdx.x * blockDim.x + threadIdx.x;
    if (idx >= BH*T_) return;
    int t  = idx & (T_-1);
    int bh = idx >> 10;
    int h  = bh & (H_-1);
    int b  = bh >> 4;

    const float4* x = (const float4*)(hs + ((size_t)(b*T_+t))*D_ + h*HD);
    float p[8];
    #pragma unroll
    for (int e = 0; e < 8; e++) p[e] = 0.f;
    #pragma unroll
    for (int i = 0; i < 16; i++) {
        float4 xv = x[i];
        #pragma unroll
        for (int e = 0; e < 8; e++) {
            const float* w = gw + e*HD + i*4;
            p[e] += xv.x*w[0] + xv.y*w[1] + xv.z*w[2] + xv.w*w[3];
        }
    }
    float pa = p[0]+p[1]+p[2]+p[3] + gb[0]+gb[1]+gb[2]+gb[3];
    float pbv= p[4]+p[5]+p[6]+p[7] + gb[4]+gb[5]+gb[6]+gb[7];
    float ga  = 1.f/(1.f + expf(-pa));
    float gbs = 1.f/(1.f + expf(-pbv));
    g_gate[idx] = ga * (gbs * gc[h] - 1.f) + 2.f;
}

// ---------------------------------------------------------------------------
// Fused flash attention — fp16, 64-row KV tiles, 2 CTAs/SM.
// QK: Qh·Kh (1-term).  PV: (Ph+Pl)·Vh (2-term).
// ---------------------------------------------------------------------------
#define FQ_B      16384                 // 128 x 64 fp16 (Q hi)
#define FKV_B     8192                  // 64 x 64 fp16 (one matrix)
#define F_STG_B   (2*FKV_B)             // Kh, Vh = 16 KB
#define F_SM_KV   FQ_B
#define F_SM_PB   (F_SM_KV + 2*F_STG_B) // 49152
#define F_SMEMT   (F_SM_PB + 2*192*4)   // 50688

__global__ __launch_bounds__(256, 2)
void flash_kernel(__half* __restrict__ outh)
{
    extern __shared__ char sm[];
    const uint32_t sb = smem_u32(sm);
    float* pb_s = (float*)(sm + F_SM_PB);

    const int tid  = threadIdx.x;
    const int lane = tid & 31, w = tid >> 5;
    const int qt = blockIdx.x, bh = blockIdx.y;
    const int b = bh >> 4, h = bh & 15;
    const size_t bhoff = (size_t)bh * T_ * HD;

    const __half* gQh = g_qh + bhoff + (size_t)qt*128*HD;

    // ---- prologue: Q + KV stage 0 + pb slice 0 ----
    #pragma unroll
    for (int i = 0; i < 4; i++) {
        int idx = tid + i * 256;
        int r = idx >> 3, c = idx & 7;
        uint32_t off = SWZ((uint32_t)(r*128 + c*16));
        cpasync16(sb + off, gQh + r*HD + c*8);
    }
    {
        const __half* src[2] = { g_kh + bhoff, g_vh + bhoff };
        #pragma unroll
        for (int mat = 0; mat < 2; mat++)
            #pragma unroll
            for (int i = 0; i < 2; i++) {
                int idx = tid + i * 256;
                int r = idx >> 3, c = idx & 7;
                uint32_t off = SWZ((uint32_t)(r*128 + c*16));
                cpasync16(sb + F_SM_KV + mat*FKV_B + off, src[mat] + r*HD + c*8);
            }
    }
    CP_COMMIT();
    if (tid < 192) pb_s[tid] = g_pb[h*2048 - qt*128 + 896 + tid];
    CP_WAIT(0);
    __syncthreads();

    // ---- Q fragments (register resident) ----
    uint32_t aQh[4][4];
    {
        const int ar = lane & 15, ac8 = lane >> 4;
        #pragma unroll
        for (int k16 = 0; k16 < 4; k16++) {
            uint32_t off = SWZ((uint32_t)((w*16 + ar)*128 + k16*32 + ac8*16));
            ldmx4(aQh[k16], sb + off);
        }
    }

    const int tg = lane >> 2, tig = lane & 3;
    const int qloc0 = w*16 + tg, qloc1 = qloc0 + 8;
    const float gate0 = g_gate[bh*T_ + qt*128 + qloc0];
    const float gate1 = g_gate[bh*T_ + qt*128 + qloc1];

    float m0 = -1e30f, m1 = -1e30f, l0 = 0.f, l1 = 0.f;
    float oacc[8][4];
    #pragma unroll
    for (int dt = 0; dt < 8; dt++)
        #pragma unroll
        for (int r = 0; r < 4; r++) oacc[dt][r] = 0.f;

    const int kb_row = (lane & 7) | ((lane & 16) >> 1);
    const int kb_c16 = (lane >> 3) & 1;
    const int v_row  = lane & 15;
    const int v_c16  = lane >> 4;

    for (int kt = 0; kt < 16; kt++) {
        const int s = kt & 1;
        // prefetch next KV stage + pb slice
        if (kt + 1 < 16) {
            const size_t koff = bhoff + (size_t)(kt+1)*64*HD;
            const __half* src[2] = { g_kh + koff, g_vh + koff };
            uint32_t sdst = sb + F_SM_KV + (s^1)*F_STG_B;
            #pragma unroll
            for (int mat = 0; mat < 2; mat++)
                #pragma unroll
                for (int i = 0; i < 2; i++) {
                    int idx = tid + i * 256;
                    int r = idx >> 3, c = idx & 7;
                    uint32_t off = SWZ((uint32_t)(r*128 + c*16));
                    cpasync16(sdst + mat*FKV_B + off, src[mat] + r*HD + c*8);
                }
            CP_COMMIT();
            if (tid < 192)
                pb_s[(s^1)*192 + tid] = g_pb[h*2048 + (kt+1)*64 - qt*128 + 896 + tid];
        }

        // ---- S = Qh·Kh, 128q x 64k ----
        const uint32_t kbh = sb + F_SM_KV + s*F_STG_B;
        float sacc[8][4];
        #pragma unroll
        for (int j = 0; j < 8; j++)
            #pragma unroll
            for (int r = 0; r < 4; r++) sacc[j][r] = 0.f;

        #pragma unroll
        for (int k16 = 0; k16 < 4; k16++) {
            #pragma unroll
            for (int np = 0; np < 4; np++) {
                uint32_t off = SWZ((uint32_t)((np*16 + kb_row)*128 + k16*32 + kb_c16*16));
                uint32_t bkh[4];
                ldmx4(bkh, kbh + off);
                mma16816(sacc[2*np],   aQh[k16], bkh);
                mma16816(sacc[2*np+1], aQh[k16], bkh+2);
            }
        }

        // ---- bias + online softmax ----
        const float* pbc = pb_s + s*192;
        float mx0 = -1e30f, mx1 = -1e30f;
        #pragma unroll
        for (int j = 0; j < 8; j++) {
            int kl0 = j*8 + 2*tig;
            sacc[j][0] += gate0 * pbc[kl0     - qloc0 + 127];
            sacc[j][1] += gate0 * pbc[kl0 + 1 - qloc0 + 127];
            sacc[j][2] += gate1 * pbc[kl0     - qloc1 + 127];
            sacc[j][3] += gate1 * pbc[kl0 + 1 - qloc1 + 127];
            mx0 = fmaxf(mx0, fmaxf(sacc[j][0], sacc[j][1]));
            mx1 = fmaxf(mx1, fmaxf(sacc[j][2], sacc[j][3]));
        }
        mx0 = fmaxf(mx0, __shfl_xor_sync(0xffffffffu, mx0, 1));
        mx0 = fmaxf(mx0, __shfl_xor_sync(0xffffffffu, mx0, 2));
        mx1 = fmaxf(mx1, __shfl_xor_sync(0xffffffffu, mx1, 1));
        mx1 = fmaxf(mx1, __shfl_xor_sync(0xffffffffu, mx1, 2));

        float nm0 = fmaxf(m0, mx0), nm1 = fmaxf(m1, mx1);
        float sc0 = __expf(m0 - nm0), sc1 = __expf(m1 - nm1);
        m0 = nm0; m1 = nm1;

        float rs0 = 0.f, rs1 = 0.f;
        #pragma unroll
        for (int j = 0; j < 8; j++) {
            sacc[j][0] = __expf(sacc[j][0] - m0);
            sacc[j][1] = __expf(sacc[j][1] - m0);
            sacc[j][2] = __expf(sacc[j][2] - m1);
            sacc[j][3] = __expf(sacc[j][3] - m1);
            rs0 += sacc[j][0] + sacc[j][1];
            rs1 += sacc[j][2] + sacc[j][3];
        }
        rs0 += __shfl_xor_sync(0xffffffffu, rs0, 1);
        rs0 += __shfl_xor_sync(0xffffffffu, rs0, 2);
        rs1 += __shfl_xor_sync(0xffffffffu, rs1, 1);
        rs1 += __shfl_xor_sync(0xffffffffu, rs1, 2);
        l0 = l0 * sc0 + rs0;
        l1 = l1 * sc1 + rs1;

        #pragma unroll
        for (int dt = 0; dt < 8; dt++) {
            oacc[dt][0] *= sc0; oacc[dt][1] *= sc0;
            oacc[dt][2] *= sc1; oacc[dt][3] *= sc1;
        }

        // ---- O += (Ph + Pl)·Vh, 64k x 64d ----
        const uint32_t vbh = kbh + FKV_B;
        #pragma unroll
        for (int kk = 0; kk < 4; kk++) {
            uint32_t ph[4], pl[4];
            split2h(sacc[2*kk][0],   sacc[2*kk][1],   ph[0], pl[0]);
            split2h(sacc[2*kk][2],   sacc[2*kk][3],   ph[1], pl[1]);
            split2h(sacc[2*kk+1][0], sacc[2*kk+1][1], ph[2], pl[2]);
            split2h(sacc[2*kk+1][2], sacc[2*kk+1][3], ph[3], pl[3]);
            #pragma unroll
            for (int dt = 0; dt < 4; dt++) {
                uint32_t off = SWZ((uint32_t)((kk*16 + v_row)*128 + dt*32 + v_c16*16));
                uint32_t bvh[4];
                ldmx4t(bvh, vbh + off);
                mma16816(oacc[2*dt],   ph, bvh);
                mma16816(oacc[2*dt],   pl, bvh);
                mma16816(oacc[2*dt+1], ph, bvh+2);
                mma16816(oacc[2*dt+1], pl, bvh+2);
            }
        }

        if (kt + 1 < 16) {
            CP_WAIT(0);
            __syncthreads();
        }
    }

    // ---- epilogue: O /= l, write fp16 hi into activation layout ----
    float il0 = 1.f / l0, il1 = 1.f / l1;
    size_t row0 = (size_t)(b*T_ + qt*128 + qloc0) * D_ + h*HD;
    size_t row1 = (size_t)(b*T_ + qt*128 + qloc1) * D_ + h*HD;
    #pragma unroll
    for (int dt = 0; dt < 8; dt++) {
        int d = dt*8 + 2*tig;
        __half2 hv0 = __floats2half2_rn(oacc[dt][0]*il0, oacc[dt][1]*il0);
        __half2 hv1 = __floats2half2_rn(oacc[dt][2]*il1, oacc[dt][3]*il1);
        *(uint32_t*)(outh + row0 + d) = *(uint32_t*)&hv0;
        *(uint32_t*)(outh + row1 + d) = *(uint32_t*)&hv1;
    }
}

// ---------------------------------------------------------------------------
extern "C" void kernel_launch(void* const* d_in, const int* in_sizes, int n_in,
                              void* d_out, int out_size)
{
    const float* hs    = (const float*)d_in[0];
    const float* q_w   = (const float*)d_in[1];
    const float* q_b   = (const float*)d_in[2];
    const float* k_w   = (const float*)d_in[3];
    const float* k_b   = (const float*)d_in[4];
    const float* v_w   = (const float*)d_in[5];
    const float* v_b   = (const float*)d_in[6];
    const float* out_w = (const float*)d_in[7];
    const float* out_b = (const float*)d_in[8];
    const float* rel   = (const float*)d_in[9];
    const float* gc    = (const float*)d_in[10];
    const float* gw    = (const float*)d_in[11];
    const float* gb    = (const float*)d_in[12];

    __half *ahi, *alo, *whi;
    cudaGetSymbolAddress((void**)&ahi, g_a_hi);
    cudaGetSymbolAddress((void**)&alo, g_a_lo);
    cudaGetSymbolAddress((void**)&whi, g_w_hi);

    cudaFuncSetAttribute(qkv_mma_kernel,
                         cudaFuncAttributeMaxDynamicSharedMemorySize, SMEMT);
    cudaFuncSetAttribute(out_mma_kernel,
                         cudaFuncAttributeMaxDynamicSharedMemorySize, SMEMT);
    cudaFuncSetAttribute(flash_kernel,
                         cudaFuncAttributeMaxDynamicSharedMemorySize, F_SMEMT);

    pb_kernel<<<8, 256>>>(rel);
    gate_kernel<<<(BH*T_)/256, 256>>>(hs, gw, gb, gc);

    const size_t WSZ = (size_t)D_*D_;
    split_kernel<<<(M_*D_/4 + 255)/256, 256>>>(hs, ahi, alo, M_*D_/4);
    splitw_kernel<<<dim3(WSZ/4/256, 4), 256>>>(q_w, k_w, v_w, out_w, whi);

    // Merged Q/K/V projection: one launch, 768 CTAs (2-term: (Ah+Al)·Wh)
    qkv_mma_kernel<<<dim3(24, 32), 256, SMEMT>>>(ahi, alo, q_b, k_b, v_b);

    // Fused attention: writes ctx (hi only) into g_a_hi
    flash_kernel<<<dim3(8, BH), 256, F_SMEMT>>>(ahi);

    // Output projection: 1-term Ah·Wh
    out_mma_kernel<<<dim3(8, 32), 256, SMEMT>>>(ahi, out_b, (float*)d_out);
}

// round 13
// speedup vs baseline: 2.1172x; 1.3616x over previous
#include <cuda_runtime.h>
#include <cuda_fp16.h>
#include <math.h>
#include <stdint.h>

// Problem constants
#define B_  4
#define T_  1024
#define D_  1024
#define H_  16
#define HD  64
#define BH  (B_*H_)     // 64
#define M_  (B_*T_)     // 4096

// Scratch (static device globals — no allocation)
__device__ float g_gate[BH*T_];               // [bh][t]
__device__ float g_pb[H_*2048];               // [h][rel+1023]

// fp16 buffers
__device__ __half g_a_hi[(size_t)M_*D_];      // activations (hs, later ctx)
__device__ __half g_w_hi[(size_t)4*D_*D_];    // 4 weight matrices
// q/k/v in [bh][t][d]
__device__ __half g_qh[(size_t)BH*T_*HD];
__device__ __half g_kh[(size_t)BH*T_*HD];
__device__ __half g_vh[(size_t)BH*T_*HD];

// ---------------------------------------------------------------------------
// PTX helpers
// ---------------------------------------------------------------------------
__device__ __forceinline__ uint32_t smem_u32(const void* p) {
    uint32_t a;
    asm("{ .reg .u64 t; cvta.to.shared.u64 t, %1; cvt.u32.u64 %0, t; }" : "=r"(a) : "l"(p));
    return a;
}
__device__ __forceinline__ void ldmx4(uint32_t* r, uint32_t addr) {
    asm volatile("ldmatrix.sync.aligned.m8n8.x4.shared.b16 {%0,%1,%2,%3}, [%4];"
        : "=r"(r[0]), "=r"(r[1]), "=r"(r[2]), "=r"(r[3]) : "r"(addr));
}
__device__ __forceinline__ void ldmx4t(uint32_t* r, uint32_t addr) {
    asm volatile("ldmatrix.sync.aligned.m8n8.x4.trans.shared.b16 {%0,%1,%2,%3}, [%4];"
        : "=r"(r[0]), "=r"(r[1]), "=r"(r[2]), "=r"(r[3]) : "r"(addr));
}
__device__ __forceinline__ void mma16816(float* c, const uint32_t* a, const uint32_t* b) {
    asm volatile("mma.sync.aligned.m16n8k16.row.col.f32.f16.f16.f32 "
        "{%0,%1,%2,%3}, {%4,%5,%6,%7}, {%8,%9}, {%0,%1,%2,%3};"
        : "+f"(c[0]), "+f"(c[1]), "+f"(c[2]), "+f"(c[3])
        : "r"(a[0]), "r"(a[1]), "r"(a[2]), "r"(a[3]), "r"(b[0]), "r"(b[1]));
}
__device__ __forceinline__ void cpasync16(uint32_t dst, const void* src) {
    asm volatile("cp.async.cg.shared.global [%0], [%1], 16;" :: "r"(dst), "l"(src));
}
#define CP_COMMIT()  asm volatile("cp.async.commit_group;" ::: "memory")
#define CP_WAIT(n)   asm volatile("cp.async.wait_group %0;" :: "n"(n) : "memory")
#define SWZ(o) ((o) ^ (((o) >> 3) & 0x70))

// ---------------------------------------------------------------------------
// Convert fp32 -> fp16: 8 matrices of 1024x1024 (4 weights + 4 hs quarters)
// ---------------------------------------------------------------------------
__global__ void cvt_kernel(const float* __restrict__ w0,
                           const float* __restrict__ w1,
                           const float* __restrict__ w2,
                           const float* __restrict__ w3,
                           const float* __restrict__ hs,
                           __half* __restrict__ whi,
                           __half* __restrict__ ahi)
{
    const int mat = blockIdx.y;
    const size_t QSZ = (size_t)D_ * D_;   // 1M elements
    const float* x;
    __half* dst;
    if (mat < 4) {
        x   = (mat == 0) ? w0 : (mat == 1) ? w1 : (mat == 2) ? w2 : w3;
        dst = whi + (size_t)mat * QSZ;
    } else {
        x   = hs + (size_t)(mat - 4) * QSZ;
        dst = ahi + (size_t)(mat - 4) * QSZ;
    }
    int i = blockIdx.x * blockDim.x + threadIdx.x;   // 0 .. QSZ/4
    float4 v = ((const float4*)x)[i];
    __half2 h0 = __floats2half2_rn(v.x, v.y);
    __half2 h1 = __floats2half2_rn(v.z, v.w);
    ((uint32_t*)dst)[2*i+0] = *(uint32_t*)&h0;
    ((uint32_t*)dst)[2*i+1] = *(uint32_t*)&h1;
}

// ---------------------------------------------------------------------------
// mma.sync projection GEMM core: C = A·W^T (pure fp16, fp32 accum)
// Stage = A tile + W tile (2 matrices, 20 KB); double buffered.
// ---------------------------------------------------------------------------
#define SST    40
#define MAT_B  (128*SST*2)        // 10240
#define STG_B  (2*MAT_B)          // 20480
#define SMEMT  (2*STG_B)          // 40960

__device__ __forceinline__ void proj_tile(
    const __half* __restrict__ A,
    const __half* __restrict__ W,
    const float* __restrict__ bias,
    float* __restrict__ outf,
    __half* __restrict__ outh,
    float scale, int remap, int m0, int n0, char* sm)
{
    const uint32_t sb = smem_u32(sm);
    const int tid = threadIdx.x;
    const int lane = tid & 31, wid = tid >> 5;
    const int wm = (wid >> 2) * 64, wn = (wid & 3) * 32;

    const __half* gsrc[2];
    gsrc[0] = A + (size_t)m0 * D_;
    gsrc[1] = W + (size_t)n0 * D_;

    auto issue = [&](int kt, int s) {
        uint32_t sdst = sb + s * STG_B;
        #pragma unroll
        for (int mat = 0; mat < 2; mat++) {
            const __half* g = gsrc[mat] + kt * 32;
            #pragma unroll
            for (int i = 0; i < 2; i++) {
                int idx = tid + i * 256;
                int r = idx >> 2, c = idx & 3;
                cpasync16(sdst + mat*MAT_B + (uint32_t)(r*SST + c*8)*2,
                          g + (size_t)r * D_ + c * 8);
            }
        }
        CP_COMMIT();
    };

    float acc[4][4][4];
    #pragma unroll
    for (int mt = 0; mt < 4; mt++)
        #pragma unroll
        for (int nt = 0; nt < 4; nt++)
            #pragma unroll
            for (int r = 0; r < 4; r++) acc[mt][nt][r] = 0.f;

    issue(0, 0);

    const int ar   = lane & 15;
    const int ac8  = lane >> 4;
    const int brow = (lane & 7) | ((lane & 16) >> 1);
    const int bc8  = (lane >> 3) & 1;

    for (int kt = 0; kt < 32; kt++) {
        const int s = kt & 1;
        if (kt + 1 < 32) { issue(kt + 1, s ^ 1); CP_WAIT(1); }
        else             { CP_WAIT(0); }
        __syncthreads();

        const uint32_t base = sb + s * STG_B;
        #pragma unroll
        for (int k16 = 0; k16 < 2; k16++) {
            uint32_t aH[4][4];
            #pragma unroll
            for (int mt = 0; mt < 4; mt++) {
                uint32_t off = (uint32_t)((wm + mt*16 + ar)*SST + k16*16 + ac8*8) * 2;
                ldmx4(aH[mt], base + 0*MAT_B + off);
            }
            #pragma unroll
            for (int np = 0; np < 2; np++) {
                uint32_t bh4[4];
                uint32_t off = (uint32_t)((wn + np*16 + brow)*SST + k16*16 + bc8*8) * 2;
                ldmx4(bh4, base + 1*MAT_B + off);
                #pragma unroll
                for (int mt = 0; mt < 4; mt++) {
                    mma16816(acc[mt][2*np],   aH[mt], bh4);
                    mma16816(acc[mt][2*np+1], aH[mt], bh4+2);
                }
            }
        }
        __syncthreads();
    }

    const int tg = lane >> 2, tig = lane & 3;
    #pragma unroll
    for (int mt = 0; mt < 4; mt++)
        #pragma unroll
        for (int i2 = 0; i2 < 2; i2++) {
            int m = m0 + wm + mt*16 + tg + i2*8;
            #pragma unroll
            for (int nt = 0; nt < 4; nt++) {
                int n = n0 + wn + nt*8 + tig*2;
                float v0 = (acc[mt][nt][i2*2+0] + bias[n])   * scale;
                float v1 = (acc[mt][nt][i2*2+1] + bias[n+1]) * scale;
                if (remap) {
                    int b = m >> 10, t = m & 1023;
                    int h = n >> 6,  d = n & 63;
                    size_t off = (((size_t)(b*H_ + h)*T_ + t))*HD + d;
                    __half2 hv = __floats2half2_rn(v0, v1);
                    *(uint32_t*)(outh + off) = *(uint32_t*)&hv;
                } else {
                    *(float2*)(outf + (size_t)m*D_ + n) = make_float2(v0, v1);
                }
            }
        }
}

// Merged Q/K/V projection: grid.x = 24 (mat = x>>3, n-block = x&7), grid.y = 32.
__global__ __launch_bounds__(256, 2)
void qkv_mma_kernel(const __half* __restrict__ A,
                    const float* __restrict__ q_b,
                    const float* __restrict__ k_b,
                    const float* __restrict__ v_b)
{
    extern __shared__ char sm[];
    const int mat = blockIdx.x >> 3;
    const int n0  = (blockIdx.x & 7) * 128;
    const int m0  = blockIdx.y * 128;
    const size_t WSZ = (size_t)D_*D_;
    const float* bias = (mat == 0) ? q_b : (mat == 1) ? k_b : v_b;
    const float scale = (mat == 0) ? 0.125f : 1.0f;
    __half* outh = (mat == 0) ? g_qh : (mat == 1) ? g_kh : g_vh;

    proj_tile(A, g_w_hi + mat*WSZ, bias, nullptr, outh, scale, 1, m0, n0, sm);
}

// Output projection (fp32 out)
__global__ __launch_bounds__(256, 2)
void out_mma_kernel(const __half* __restrict__ A,
                    const float* __restrict__ bias,
                    float* __restrict__ out)
{
    extern __shared__ char sm[];
    const size_t WSZ = (size_t)D_*D_;
    proj_tile(A, g_w_hi + 3*WSZ, bias, out, nullptr, 1.0f, 0,
              blockIdx.y * 128, blockIdx.x * 128, sm);
}

// ---------------------------------------------------------------------------
// Position-bias LUT
// ---------------------------------------------------------------------------
__global__ void pb_kernel(const float* __restrict__ rel_embed)
{
    int d = blockIdx.x * blockDim.x + threadIdx.x;
    if (d >= 2047) return;
    int rel = d - 1023;
    int rb  = (rel > 0) ? 160 : 0;
    int rp  = rel < 0 ? -rel : rel;
    int bucket;
    if (rp < 80) {
        bucket = rb + rp;
    } else {
        float t = logf((float)rp / 80.0f) / logf(10.0f);
        t = t * 80.0f;
        float v = 80.0f + t;
        int bi = (int)v;
        bucket = rb + (bi < 159 ? bi : 159);
    }
    #pragma unroll
    for (int h = 0; h < H_; h++)
        g_pb[h*2048 + d] = rel_embed[bucket*H_ + h];
}

// ---------------------------------------------------------------------------
// Gate
// ---------------------------------------------------------------------------
__global__ void gate_kernel(const float* __restrict__ hs,
                            const float* __restrict__ gw,
                            const float* __restrict__ gb,
                            const float* __restrict__ gc)
{
    int idx = blockIdx.x * blockDim.x + threadIdx.x;
    if (idx >= BH*T_) return;
    int t  = idx & (T_-1);
    int bh = idx >> 10;
    int h  = bh & (H_-1);
    int b  = bh >> 4;

    const float4* x = (const float4*)(hs + ((size_t)(b*T_+t))*D_ + h*HD);
    float p[8];
    #pragma unroll
    for (int e = 0; e < 8; e++) p[e] = 0.f;
    #pragma unroll
    for (int i = 0; i < 16; i++) {
        float4 xv = x[i];
        #pragma unroll
        for (int e = 0; e < 8; e++) {
            const float* w = gw + e*HD + i*4;
            p[e] += xv.x*w[0] + xv.y*w[1] + xv.z*w[2] + xv.w*w[3];
        }
    }
    float pa = p[0]+p[1]+p[2]+p[3] + gb[0]+gb[1]+gb[2]+gb[3];
    float pbv= p[4]+p[5]+p[6]+p[7] + gb[4]+gb[5]+gb[6]+gb[7];
    float ga  = 1.f/(1.f + expf(-pa));
    float gbs = 1.f/(1.f + expf(-pbv));
    g_gate[idx] = ga * (gbs * gc[h] - 1.f) + 2.f;
}

// ---------------------------------------------------------------------------
// Fused flash attention — pure fp16 mma, 64-row KV tiles, 2 CTAs/SM.
// QK: Qh·Kh.  PV: Ph·Vh.
// ---------------------------------------------------------------------------
#define FQ_B      16384                 // 128 x 64 fp16 (Q)
#define FKV_B     8192                  // 64 x 64 fp16 (one matrix)
#define F_STG_B   (2*FKV_B)             // K, V = 16 KB
#define F_SM_KV   FQ_B
#define F_SM_PB   (F_SM_KV + 2*F_STG_B) // 49152
#define F_SMEMT   (F_SM_PB + 2*192*4)   // 50688

__global__ __launch_bounds__(256, 2)
void flash_kernel(__half* __restrict__ outh)
{
    extern __shared__ char sm[];
    const uint32_t sb = smem_u32(sm);
    float* pb_s = (float*)(sm + F_SM_PB);

    const int tid  = threadIdx.x;
    const int lane = tid & 31, w = tid >> 5;
    const int qt = blockIdx.x, bh = blockIdx.y;
    const int b = bh >> 4, h = bh & 15;
    const size_t bhoff = (size_t)bh * T_ * HD;

    const __half* gQh = g_qh + bhoff + (size_t)qt*128*HD;

    // ---- prologue: Q + KV stage 0 + pb slice 0 ----
    #pragma unroll
    for (int i = 0; i < 4; i++) {
        int idx = tid + i * 256;
        int r = idx >> 3, c = idx & 7;
        uint32_t off = SWZ((uint32_t)(r*128 + c*16));
        cpasync16(sb + off, gQh + r*HD + c*8);
    }
    {
        const __half* src[2] = { g_kh + bhoff, g_vh + bhoff };
        #pragma unroll
        for (int mat = 0; mat < 2; mat++)
            #pragma unroll
            for (int i = 0; i < 2; i++) {
                int idx = tid + i * 256;
                int r = idx >> 3, c = idx & 7;
                uint32_t off = SWZ((uint32_t)(r*128 + c*16));
                cpasync16(sb + F_SM_KV + mat*FKV_B + off, src[mat] + r*HD + c*8);
            }
    }
    CP_COMMIT();
    if (tid < 192) pb_s[tid] = g_pb[h*2048 - qt*128 + 896 + tid];
    CP_WAIT(0);
    __syncthreads();

    // ---- Q fragments (register resident) ----
    uint32_t aQh[4][4];
    {
        const int ar = lane & 15, ac8 = lane >> 4;
        #pragma unroll
        for (int k16 = 0; k16 < 4; k16++) {
            uint32_t off = SWZ((uint32_t)((w*16 + ar)*128 + k16*32 + ac8*16));
            ldmx4(aQh[k16], sb + off);
        }
    }

    const int tg = lane >> 2, tig = lane & 3;
    const int qloc0 = w*16 + tg, qloc1 = qloc0 + 8;
    const float gate0 = g_gate[bh*T_ + qt*128 + qloc0];
    const float gate1 = g_gate[bh*T_ + qt*128 + qloc1];

    float m0 = -1e30f, m1 = -1e30f, l0 = 0.f, l1 = 0.f;
    float oacc[8][4];
    #pragma unroll
    for (int dt = 0; dt < 8; dt++)
        #pragma unroll
        for (int r = 0; r < 4; r++) oacc[dt][r] = 0.f;

    const int kb_row = (lane & 7) | ((lane & 16) >> 1);
    const int kb_c16 = (lane >> 3) & 1;
    const int v_row  = lane & 15;
    const int v_c16  = lane >> 4;

    for (int kt = 0; kt < 16; kt++) {
        const int s = kt & 1;
        // prefetch next KV stage + pb slice
        if (kt + 1 < 16) {
            const size_t koff = bhoff + (size_t)(kt+1)*64*HD;
            const __half* src[2] = { g_kh + koff, g_vh + koff };
            uint32_t sdst = sb + F_SM_KV + (s^1)*F_STG_B;
            #pragma unroll
            for (int mat = 0; mat < 2; mat++)
                #pragma unroll
                for (int i = 0; i < 2; i++) {
                    int idx = tid + i * 256;
                    int r = idx >> 3, c = idx & 7;
                    uint32_t off = SWZ((uint32_t)(r*128 + c*16));
                    cpasync16(sdst + mat*FKV_B + off, src[mat] + r*HD + c*8);
                }
            CP_COMMIT();
            if (tid < 192)
                pb_s[(s^1)*192 + tid] = g_pb[h*2048 + (kt+1)*64 - qt*128 + 896 + tid];
        }

        // ---- S = Qh·Kh, 128q x 64k ----
        const uint32_t kbh = sb + F_SM_KV + s*F_STG_B;
        float sacc[8][4];
        #pragma unroll
        for (int j = 0; j < 8; j++)
            #pragma unroll
            for (int r = 0; r < 4; r++) sacc[j][r] = 0.f;

        #pragma unroll
        for (int k16 = 0; k16 < 4; k16++) {
            #pragma unroll
            for (int np = 0; np < 4; np++) {
                uint32_t off = SWZ((uint32_t)((np*16 + kb_row)*128 + k16*32 + kb_c16*16));
                uint32_t bkh[4];
                ldmx4(bkh, kbh + off);
                mma16816(sacc[2*np],   aQh[k16], bkh);
                mma16816(sacc[2*np+1], aQh[k16], bkh+2);
            }
        }

        // ---- bias + online softmax ----
        const float* pbc = pb_s + s*192;
        float mx0 = -1e30f, mx1 = -1e30f;
        #pragma unroll
        for (int j = 0; j < 8; j++) {
            int kl0 = j*8 + 2*tig;
            sacc[j][0] += gate0 * pbc[kl0     - qloc0 + 127];
            sacc[j][1] += gate0 * pbc[kl0 + 1 - qloc0 + 127];
            sacc[j][2] += gate1 * pbc[kl0     - qloc1 + 127];
            sacc[j][3] += gate1 * pbc[kl0 + 1 - qloc1 + 127];
            mx0 = fmaxf(mx0, fmaxf(sacc[j][0], sacc[j][1]));
            mx1 = fmaxf(mx1, fmaxf(sacc[j][2], sacc[j][3]));
        }
        mx0 = fmaxf(mx0, __shfl_xor_sync(0xffffffffu, mx0, 1));
        mx0 = fmaxf(mx0, __shfl_xor_sync(0xffffffffu, mx0, 2));
        mx1 = fmaxf(mx1, __shfl_xor_sync(0xffffffffu, mx1, 1));
        mx1 = fmaxf(mx1, __shfl_xor_sync(0xffffffffu, mx1, 2));

        float nm0 = fmaxf(m0, mx0), nm1 = fmaxf(m1, mx1);
        float sc0 = __expf(m0 - nm0), sc1 = __expf(m1 - nm1);
        m0 = nm0; m1 = nm1;

        float rs0 = 0.f, rs1 = 0.f;
        #pragma unroll
        for (int j = 0; j < 8; j++) {
            sacc[j][0] = __expf(sacc[j][0] - m0);
            sacc[j][1] = __expf(sacc[j][1] - m0);
            sacc[j][2] = __expf(sacc[j][2] - m1);
            sacc[j][3] = __expf(sacc[j][3] - m1);
            rs0 += sacc[j][0] + sacc[j][1];
            rs1 += sacc[j][2] + sacc[j][3];
        }
        rs0 += __shfl_xor_sync(0xffffffffu, rs0, 1);
        rs0 += __shfl_xor_sync(0xffffffffu, rs0, 2);
        rs1 += __shfl_xor_sync(0xffffffffu, rs1, 1);
        rs1 += __shfl_xor_sync(0xffffffffu, rs1, 2);
        l0 = l0 * sc0 + rs0;
        l1 = l1 * sc1 + rs1;

        #pragma unroll
        for (int dt = 0; dt < 8; dt++) {
            oacc[dt][0] *= sc0; oacc[dt][1] *= sc0;
            oacc[dt][2] *= sc1; oacc[dt][3] *= sc1;
        }

        // ---- O += Ph·Vh, 64k x 64d ----
        const uint32_t vbh = kbh + FKV_B;
        #pragma unroll
        for (int kk = 0; kk < 4; kk++) {
            uint32_t ph[4];
            __half2 p0 = __floats2half2_rn(sacc[2*kk][0],   sacc[2*kk][1]);
            __half2 p1 = __floats2half2_rn(sacc[2*kk][2],   sacc[2*kk][3]);
            __half2 p2 = __floats2half2_rn(sacc[2*kk+1][0], sacc[2*kk+1][1]);
            __half2 p3 = __floats2half2_rn(sacc[2*kk+1][2], sacc[2*kk+1][3]);
            ph[0] = *(uint32_t*)&p0; ph[1] = *(uint32_t*)&p1;
            ph[2] = *(uint32_t*)&p2; ph[3] = *(uint32_t*)&p3;
            #pragma unroll
            for (int dt = 0; dt < 4; dt++) {
                uint32_t off = SWZ((uint32_t)((kk*16 + v_row)*128 + dt*32 + v_c16*16));
                uint32_t bvh[4];
                ldmx4t(bvh, vbh + off);
                mma16816(oacc[2*dt],   ph, bvh);
                mma16816(oacc[2*dt+1], ph, bvh+2);
            }
        }

        if (kt + 1 < 16) {
            CP_WAIT(0);
            __syncthreads();
        }
    }

    // ---- epilogue: O /= l, write fp16 into activation layout ----
    float il0 = 1.f / l0, il1 = 1.f / l1;
    size_t row0 = (size_t)(b*T_ + qt*128 + qloc0) * D_ + h*HD;
    size_t row1 = (size_t)(b*T_ + qt*128 + qloc1) * D_ + h*HD;
    #pragma unroll
    for (int dt = 0; dt < 8; dt++) {
        int d = dt*8 + 2*tig;
        __half2 hv0 = __floats2half2_rn(oacc[dt][0]*il0, oacc[dt][1]*il0);
        __half2 hv1 = __floats2half2_rn(oacc[dt][2]*il1, oacc[dt][3]*il1);
        *(uint32_t*)(outh + row0 + d) = *(uint32_t*)&hv0;
        *(uint32_t*)(outh + row1 + d) = *(uint32_t*)&hv1;
    }
}

// ---------------------------------------------------------------------------
extern "C" void kernel_launch(void* const* d_in, const int* in_sizes, int n_in,
                              void* d_out, int out_size)
{
    const float* hs    = (const float*)d_in[0];
    const float* q_w   = (const float*)d_in[1];
    const float* q_b   = (const float*)d_in[2];
    const float* k_w   = (const float*)d_in[3];
    const float* k_b   = (const float*)d_in[4];
    const float* v_w   = (const float*)d_in[5];
    const float* v_b   = (const float*)d_in[6];
    const float* out_w = (const float*)d_in[7];
    const float* out_b = (const float*)d_in[8];
    const float* rel   = (const float*)d_in[9];
    const float* gc    = (const float*)d_in[10];
    const float* gw    = (const float*)d_in[11];
    const float* gb    = (const float*)d_in[12];

    __half *ahi, *whi;
    cudaGetSymbolAddress((void**)&ahi, g_a_hi);
    cudaGetSymbolAddress((void**)&whi, g_w_hi);

    cudaFuncSetAttribute(qkv_mma_kernel,
                         cudaFuncAttributeMaxDynamicSharedMemorySize, SMEMT);
    cudaFuncSetAttribute(out_mma_kernel,
                         cudaFuncAttributeMaxDynamicSharedMemorySize, SMEMT);
    cudaFuncSetAttribute(flash_kernel,
                         cudaFuncAttributeMaxDynamicSharedMemorySize, F_SMEMT);

    pb_kernel<<<8, 256>>>(rel);
    gate_kernel<<<(BH*T_)/256, 256>>>(hs, gw, gb, gc);

    // Convert weights (4) + hs (4 quarters) to fp16 in one launch
    cvt_kernel<<<dim3(D_*D_/4/256, 8), 256>>>(q_w, k_w, v_w, out_w, hs, whi, ahi);

    // Merged Q/K/V projection (1-term fp16): one launch, 768 CTAs
    qkv_mma_kernel<<<dim3(24, 32), 256, SMEMT>>>(ahi, q_b, k_b, v_b);

    // Fused attention: writes ctx into g_a_hi
    flash_kernel<<<dim3(8, BH), 256, F_SMEMT>>>(ahi);

    // Output projection (1-term fp16)
    out_mma_kernel<<<dim3(8, 32), 256, SMEMT>>>(ahi, out_b, (float*)d_out);
}

// round 14
// speedup vs baseline: 2.2971x; 1.0850x over previous
#include <cuda_runtime.h>
#include <cuda_fp16.h>
#include <math.h>
#include <stdint.h>

// Problem constants
#define B_  4
#define T_  1024
#define D_  1024
#define H_  16
#define HD  64
#define BH  (B_*H_)     // 64
#define M_  (B_*T_)     // 4096

// Scratch (static device globals — no allocation)
__device__ float g_gate[BH*T_];               // [bh][t]
__device__ float g_pb[H_*2048];               // [h][rel+1023]

// fp16 buffers
__device__ __half g_a_hi[(size_t)M_*D_];      // activations (hs, later ctx)
__device__ __half g_w_hi[(size_t)4*D_*D_];    // 4 weight matrices
// q/k/v in [bh][t][d]
__device__ __half g_qh[(size_t)BH*T_*HD];
__device__ __half g_kh[(size_t)BH*T_*HD];
__device__ __half g_vh[(size_t)BH*T_*HD];

// ---------------------------------------------------------------------------
// PTX helpers
// ---------------------------------------------------------------------------
__device__ __forceinline__ uint32_t smem_u32(const void* p) {
    uint32_t a;
    asm("{ .reg .u64 t; cvta.to.shared.u64 t, %1; cvt.u32.u64 %0, t; }" : "=r"(a) : "l"(p));
    return a;
}
__device__ __forceinline__ void ldmx4(uint32_t* r, uint32_t addr) {
    asm volatile("ldmatrix.sync.aligned.m8n8.x4.shared.b16 {%0,%1,%2,%3}, [%4];"
        : "=r"(r[0]), "=r"(r[1]), "=r"(r[2]), "=r"(r[3]) : "r"(addr));
}
__device__ __forceinline__ void ldmx4t(uint32_t* r, uint32_t addr) {
    asm volatile("ldmatrix.sync.aligned.m8n8.x4.trans.shared.b16 {%0,%1,%2,%3}, [%4];"
        : "=r"(r[0]), "=r"(r[1]), "=r"(r[2]), "=r"(r[3]) : "r"(addr));
}
__device__ __forceinline__ void mma16816(float* c, const uint32_t* a, const uint32_t* b) {
    asm volatile("mma.sync.aligned.m16n8k16.row.col.f32.f16.f16.f32 "
        "{%0,%1,%2,%3}, {%4,%5,%6,%7}, {%8,%9}, {%0,%1,%2,%3};"
        : "+f"(c[0]), "+f"(c[1]), "+f"(c[2]), "+f"(c[3])
        : "r"(a[0]), "r"(a[1]), "r"(a[2]), "r"(a[3]), "r"(b[0]), "r"(b[1]));
}
__device__ __forceinline__ void cpasync16(uint32_t dst, const void* src) {
    asm volatile("cp.async.cg.shared.global [%0], [%1], 16;" :: "r"(dst), "l"(src));
}
#define CP_COMMIT()  asm volatile("cp.async.commit_group;" ::: "memory")
#define CP_WAIT(n)   asm volatile("cp.async.wait_group %0;" :: "n"(n) : "memory")
#define SWZ(o) ((o) ^ (((o) >> 3) & 0x70))

// ---------------------------------------------------------------------------
// Convert fp32 -> fp16: 8 matrices of 1024x1024 (4 weights + 4 hs quarters)
// ---------------------------------------------------------------------------
__global__ void cvt_kernel(const float* __restrict__ w0,
                           const float* __restrict__ w1,
                           const float* __restrict__ w2,
                           const float* __restrict__ w3,
                           const float* __restrict__ hs,
                           __half* __restrict__ whi,
                           __half* __restrict__ ahi)
{
    const int mat = blockIdx.y;
    const size_t QSZ = (size_t)D_ * D_;
    const float* x;
    __half* dst;
    if (mat < 4) {
        x   = (mat == 0) ? w0 : (mat == 1) ? w1 : (mat == 2) ? w2 : w3;
        dst = whi + (size_t)mat * QSZ;
    } else {
        x   = hs + (size_t)(mat - 4) * QSZ;
        dst = ahi + (size_t)(mat - 4) * QSZ;
    }
    int i = blockIdx.x * blockDim.x + threadIdx.x;
    float4 v = ((const float4*)x)[i];
    __half2 h0 = __floats2half2_rn(v.x, v.y);
    __half2 h1 = __floats2half2_rn(v.z, v.w);
    ((uint32_t*)dst)[2*i+0] = *(uint32_t*)&h0;
    ((uint32_t*)dst)[2*i+1] = *(uint32_t*)&h1;
}

// ---------------------------------------------------------------------------
// mma.sync projection GEMM core: C = A·W^T (pure fp16, fp32 accum)
// BK = 64: stage = A(128x64) + W(128x64), double-buffered; 16 kt iterations.
// ---------------------------------------------------------------------------
#define SST    72                 // 64 data + 8 pad halves (144B row stride)
#define MAT_B  (128*SST*2)        // 18432
#define STG_B  (2*MAT_B)          // 36864
#define SMEMT  (2*STG_B)          // 73728 (x2 CTAs = 144 KB <= 228 KB/SM)

__device__ __forceinline__ void proj_tile(
    const __half* __restrict__ A,
    const __half* __restrict__ W,
    const float* __restrict__ bias,
    float* __restrict__ outf,
    __half* __restrict__ outh,
    float scale, int remap, int m0, int n0, char* sm)
{
    const uint32_t sb = smem_u32(sm);
    const int tid = threadIdx.x;
    const int lane = tid & 31, wid = tid >> 5;
    const int wm = (wid >> 2) * 64, wn = (wid & 3) * 32;

    const __half* gsrc[2];
    gsrc[0] = A + (size_t)m0 * D_;
    gsrc[1] = W + (size_t)n0 * D_;

    auto issue = [&](int kt, int s) {
        uint32_t sdst = sb + s * STG_B;
        #pragma unroll
        for (int mat = 0; mat < 2; mat++) {
            const __half* g = gsrc[mat] + kt * 64;
            #pragma unroll
            for (int i = 0; i < 4; i++) {
                int idx = tid + i * 256;           // 0..1023
                int r = idx >> 3, c = idx & 7;     // 128 rows x 8 chunks
                cpasync16(sdst + mat*MAT_B + (uint32_t)(r*SST + c*8)*2,
                          g + (size_t)r * D_ + c * 8);
            }
        }
        CP_COMMIT();
    };

    float acc[4][4][4];
    #pragma unroll
    for (int mt = 0; mt < 4; mt++)
        #pragma unroll
        for (int nt = 0; nt < 4; nt++)
            #pragma unroll
            for (int r = 0; r < 4; r++) acc[mt][nt][r] = 0.f;

    issue(0, 0);

    const int ar   = lane & 15;
    const int ac8  = lane >> 4;
    const int brow = (lane & 7) | ((lane & 16) >> 1);
    const int bc8  = (lane >> 3) & 1;

    for (int kt = 0; kt < 16; kt++) {
        const int s = kt & 1;
        if (kt + 1 < 16) { issue(kt + 1, s ^ 1); CP_WAIT(1); }
        else             { CP_WAIT(0); }
        __syncthreads();

        const uint32_t base = sb + s * STG_B;
        #pragma unroll
        for (int k16 = 0; k16 < 4; k16++) {
            uint32_t aH[4][4];
            #pragma unroll
            for (int mt = 0; mt < 4; mt++) {
                uint32_t off = (uint32_t)((wm + mt*16 + ar)*SST + k16*16 + ac8*8) * 2;
                ldmx4(aH[mt], base + 0*MAT_B + off);
            }
            #pragma unroll
            for (int np = 0; np < 2; np++) {
                uint32_t bh4[4];
                uint32_t off = (uint32_t)((wn + np*16 + brow)*SST + k16*16 + bc8*8) * 2;
                ldmx4(bh4, base + 1*MAT_B + off);
                #pragma unroll
                for (int mt = 0; mt < 4; mt++) {
                    mma16816(acc[mt][2*np],   aH[mt], bh4);
                    mma16816(acc[mt][2*np+1], aH[mt], bh4+2);
                }
            }
        }
        __syncthreads();
    }

    const int tg = lane >> 2, tig = lane & 3;
    #pragma unroll
    for (int mt = 0; mt < 4; mt++)
        #pragma unroll
        for (int i2 = 0; i2 < 2; i2++) {
            int m = m0 + wm + mt*16 + tg + i2*8;
            #pragma unroll
            for (int nt = 0; nt < 4; nt++) {
                int n = n0 + wn + nt*8 + tig*2;
                float v0 = (acc[mt][nt][i2*2+0] + bias[n])   * scale;
                float v1 = (acc[mt][nt][i2*2+1] + bias[n+1]) * scale;
                if (remap) {
                    int b = m >> 10, t = m & 1023;
                    int h = n >> 6,  d = n & 63;
                    size_t off = (((size_t)(b*H_ + h)*T_ + t))*HD + d;
                    __half2 hv = __floats2half2_rn(v0, v1);
                    *(uint32_t*)(outh + off) = *(uint32_t*)&hv;
                } else {
                    *(float2*)(outf + (size_t)m*D_ + n) = make_float2(v0, v1);
                }
            }
        }
}

// Merged Q/K/V projection: grid.x = 24 (mat = x>>3, n-block = x&7), grid.y = 32.
__global__ __launch_bounds__(256, 2)
void qkv_mma_kernel(const __half* __restrict__ A,
                    const float* __restrict__ q_b,
                    const float* __restrict__ k_b,
                    const float* __restrict__ v_b)
{
    extern __shared__ char sm[];
    const int mat = blockIdx.x >> 3;
    const int n0  = (blockIdx.x & 7) * 128;
    const int m0  = blockIdx.y * 128;
    const size_t WSZ = (size_t)D_*D_;
    const float* bias = (mat == 0) ? q_b : (mat == 1) ? k_b : v_b;
    const float scale = (mat == 0) ? 0.125f : 1.0f;
    __half* outh = (mat == 0) ? g_qh : (mat == 1) ? g_kh : g_vh;

    proj_tile(A, g_w_hi + mat*WSZ, bias, nullptr, outh, scale, 1, m0, n0, sm);
}

// Output projection (fp32 out)
__global__ __launch_bounds__(256, 2)
void out_mma_kernel(const __half* __restrict__ A,
                    const float* __restrict__ bias,
                    float* __restrict__ out)
{
    extern __shared__ char sm[];
    const size_t WSZ = (size_t)D_*D_;
    proj_tile(A, g_w_hi + 3*WSZ, bias, out, nullptr, 1.0f, 0,
              blockIdx.y * 128, blockIdx.x * 128, sm);
}

// ---------------------------------------------------------------------------
// Position-bias LUT
// ---------------------------------------------------------------------------
__global__ void pb_kernel(const float* __restrict__ rel_embed)
{
    int d = blockIdx.x * blockDim.x + threadIdx.x;
    if (d >= 2047) return;
    int rel = d - 1023;
    int rb  = (rel > 0) ? 160 : 0;
    int rp  = rel < 0 ? -rel : rel;
    int bucket;
    if (rp < 80) {
        bucket = rb + rp;
    } else {
        float t = logf((float)rp / 80.0f) / logf(10.0f);
        t = t * 80.0f;
        float v = 80.0f + t;
        int bi = (int)v;
        bucket = rb + (bi < 159 ? bi : 159);
    }
    #pragma unroll
    for (int h = 0; h < H_; h++)
        g_pb[h*2048 + d] = rel_embed[bucket*H_ + h];
}

// ---------------------------------------------------------------------------
// Gate
// ---------------------------------------------------------------------------
__global__ void gate_kernel(const float* __restrict__ hs,
                            const float* __restrict__ gw,
                            const float* __restrict__ gb,
                            const float* __restrict__ gc)
{
    int idx = blockIdx.x * blockDim.x + threadIdx.x;
    if (idx >= BH*T_) return;
    int t  = idx & (T_-1);
    int bh = idx >> 10;
    int h  = bh & (H_-1);
    int b  = bh >> 4;

    const float4* x = (const float4*)(hs + ((size_t)(b*T_+t))*D_ + h*HD);
    float p[8];
    #pragma unroll
    for (int e = 0; e < 8; e++) p[e] = 0.f;
    #pragma unroll
    for (int i = 0; i < 16; i++) {
        float4 xv = x[i];
        #pragma unroll
        for (int e = 0; e < 8; e++) {
            const float* w = gw + e*HD + i*4;
            p[e] += xv.x*w[0] + xv.y*w[1] + xv.z*w[2] + xv.w*w[3];
        }
    }
    float pa = p[0]+p[1]+p[2]+p[3] + gb[0]+gb[1]+gb[2]+gb[3];
    float pbv= p[4]+p[5]+p[6]+p[7] + gb[4]+gb[5]+gb[6]+gb[7];
    float ga  = 1.f/(1.f + expf(-pa));
    float gbs = 1.f/(1.f + expf(-pbv));
    g_gate[idx] = ga * (gbs * gc[h] - 1.f) + 2.f;
}

// ---------------------------------------------------------------------------
// Fused flash attention — pure fp16 mma, 64-row KV tiles, 2 CTAs/SM.
// QK: Qh·Kh.  PV: Ph·Vh.
// ---------------------------------------------------------------------------
#define FQ_B      16384                 // 128 x 64 fp16 (Q)
#define FKV_B     8192                  // 64 x 64 fp16 (one matrix)
#define F_STG_B   (2*FKV_B)             // K, V = 16 KB
#define F_SM_KV   FQ_B
#define F_SM_PB   (F_SM_KV + 2*F_STG_B) // 49152
#define F_SMEMT   (F_SM_PB + 2*192*4)   // 50688

__global__ __launch_bounds__(256, 2)
void flash_kernel(__half* __restrict__ outh)
{
    extern __shared__ char sm[];
    const uint32_t sb = smem_u32(sm);
    float* pb_s = (float*)(sm + F_SM_PB);

    const int tid  = threadIdx.x;
    const int lane = tid & 31, w = tid >> 5;
    const int qt = blockIdx.x, bh = blockIdx.y;
    const int b = bh >> 4, h = bh & 15;
    const size_t bhoff = (size_t)bh * T_ * HD;

    const __half* gQh = g_qh + bhoff + (size_t)qt*128*HD;

    // ---- prologue: Q + KV stage 0 + pb slice 0 ----
    #pragma unroll
    for (int i = 0; i < 4; i++) {
        int idx = tid + i * 256;
        int r = idx >> 3, c = idx & 7;
        uint32_t off = SWZ((uint32_t)(r*128 + c*16));
        cpasync16(sb + off, gQh + r*HD + c*8);
    }
    {
        const __half* src[2] = { g_kh + bhoff, g_vh + bhoff };
        #pragma unroll
        for (int mat = 0; mat < 2; mat++)
            #pragma unroll
            for (int i = 0; i < 2; i++) {
                int idx = tid + i * 256;
                int r = idx >> 3, c = idx & 7;
                uint32_t off = SWZ((uint32_t)(r*128 + c*16));
                cpasync16(sb + F_SM_KV + mat*FKV_B + off, src[mat] + r*HD + c*8);
            }
    }
    CP_COMMIT();
    if (tid < 192) pb_s[tid] = g_pb[h*2048 - qt*128 + 896 + tid];
    CP_WAIT(0);
    __syncthreads();

    // ---- Q fragments (register resident) ----
    uint32_t aQh[4][4];
    {
        const int ar = lane & 15, ac8 = lane >> 4;
        #pragma unroll
        for (int k16 = 0; k16 < 4; k16++) {
            uint32_t off = SWZ((uint32_t)((w*16 + ar)*128 + k16*32 + ac8*16));
            ldmx4(aQh[k16], sb + off);
        }
    }

    const int tg = lane >> 2, tig = lane & 3;
    const int qloc0 = w*16 + tg, qloc1 = qloc0 + 8;
    const float gate0 = g_gate[bh*T_ + qt*128 + qloc0];
    const float gate1 = g_gate[bh*T_ + qt*128 + qloc1];

    float m0 = -1e30f, m1 = -1e30f, l0 = 0.f, l1 = 0.f;
    float oacc[8][4];
    #pragma unroll
    for (int dt = 0; dt < 8; dt++)
        #pragma unroll
        for (int r = 0; r < 4; r++) oacc[dt][r] = 0.f;

    const int kb_row = (lane & 7) | ((lane & 16) >> 1);
    const int kb_c16 = (lane >> 3) & 1;
    const int v_row  = lane & 15;
    const int v_c16  = lane >> 4;

    for (int kt = 0; kt < 16; kt++) {
        const int s = kt & 1;
        // prefetch next KV stage + pb slice
        if (kt + 1 < 16) {
            const size_t koff = bhoff + (size_t)(kt+1)*64*HD;
            const __half* src[2] = { g_kh + koff, g_vh + koff };
            uint32_t sdst = sb + F_SM_KV + (s^1)*F_STG_B;
            #pragma unroll
            for (int mat = 0; mat < 2; mat++)
                #pragma unroll
                for (int i = 0; i < 2; i++) {
                    int idx = tid + i * 256;
                    int r = idx >> 3, c = idx & 7;
                    uint32_t off = SWZ((uint32_t)(r*128 + c*16));
                    cpasync16(sdst + mat*FKV_B + off, src[mat] + r*HD + c*8);
                }
            CP_COMMIT();
            if (tid < 192)
                pb_s[(s^1)*192 + tid] = g_pb[h*2048 + (kt+1)*64 - qt*128 + 896 + tid];
        }

        // ---- S = Qh·Kh, 128q x 64k ----
        const uint32_t kbh = sb + F_SM_KV + s*F_STG_B;
        float sacc[8][4];
        #pragma unroll
        for (int j = 0; j < 8; j++)
            #pragma unroll
            for (int r = 0; r < 4; r++) sacc[j][r] = 0.f;

        #pragma unroll
        for (int k16 = 0; k16 < 4; k16++) {
            #pragma unroll
            for (int np = 0; np < 4; np++) {
                uint32_t off = SWZ((uint32_t)((np*16 + kb_row)*128 + k16*32 + kb_c16*16));
                uint32_t bkh[4];
                ldmx4(bkh, kbh + off);
                mma16816(sacc[2*np],   aQh[k16], bkh);
                mma16816(sacc[2*np+1], aQh[k16], bkh+2);
            }
        }

        // ---- bias + online softmax ----
        const float* pbc = pb_s + s*192;
        float mx0 = -1e30f, mx1 = -1e30f;
        #pragma unroll
        for (int j = 0; j < 8; j++) {
            int kl0 = j*8 + 2*tig;
            sacc[j][0] += gate0 * pbc[kl0     - qloc0 + 127];
            sacc[j][1] += gate0 * pbc[kl0 + 1 - qloc0 + 127];
            sacc[j][2] += gate1 * pbc[kl0     - qloc1 + 127];
            sacc[j][3] += gate1 * pbc[kl0 + 1 - qloc1 + 127];
            mx0 = fmaxf(mx0, fmaxf(sacc[j][0], sacc[j][1]));
            mx1 = fmaxf(mx1, fmaxf(sacc[j][2], sacc[j][3]));
        }
        mx0 = fmaxf(mx0, __shfl_xor_sync(0xffffffffu, mx0, 1));
        mx0 = fmaxf(mx0, __shfl_xor_sync(0xffffffffu, mx0, 2));
        mx1 = fmaxf(mx1, __shfl_xor_sync(0xffffffffu, mx1, 1));
        mx1 = fmaxf(mx1, __shfl_xor_sync(0xffffffffu, mx1, 2));

        float nm0 = fmaxf(m0, mx0), nm1 = fmaxf(m1, mx1);
        float sc0 = __expf(m0 - nm0), sc1 = __expf(m1 - nm1);
        m0 = nm0; m1 = nm1;

        float rs0 = 0.f, rs1 = 0.f;
        #pragma unroll
        for (int j = 0; j < 8; j++) {
            sacc[j][0] = __expf(sacc[j][0] - m0);
            sacc[j][1] = __expf(sacc[j][1] - m0);
            sacc[j][2] = __expf(sacc[j][2] - m1);
            sacc[j][3] = __expf(sacc[j][3] - m1);
            rs0 += sacc[j][0] + sacc[j][1];
            rs1 += sacc[j][2] + sacc[j][3];
        }
        rs0 += __shfl_xor_sync(0xffffffffu, rs0, 1);
        rs0 += __shfl_xor_sync(0xffffffffu, rs0, 2);
        rs1 += __shfl_xor_sync(0xffffffffu, rs1, 1);
        rs1 += __shfl_xor_sync(0xffffffffu, rs1, 2);
        l0 = l0 * sc0 + rs0;
        l1 = l1 * sc1 + rs1;

        #pragma unroll
        for (int dt = 0; dt < 8; dt++) {
            oacc[dt][0] *= sc0; oacc[dt][1] *= sc0;
            oacc[dt][2] *= sc1; oacc[dt][3] *= sc1;
        }

        // ---- O += Ph·Vh, 64k x 64d ----
        const uint32_t vbh = kbh + FKV_B;
        #pragma unroll
        for (int kk = 0; kk < 4; kk++) {
            uint32_t ph[4];
            __half2 p0 = __floats2half2_rn(sacc[2*kk][0],   sacc[2*kk][1]);
            __half2 p1 = __floats2half2_rn(sacc[2*kk][2],   sacc[2*kk][3]);
            __half2 p2 = __floats2half2_rn(sacc[2*kk+1][0], sacc[2*kk+1][1]);
            __half2 p3 = __floats2half2_rn(sacc[2*kk+1][2], sacc[2*kk+1][3]);
            ph[0] = *(uint32_t*)&p0; ph[1] = *(uint32_t*)&p1;
            ph[2] = *(uint32_t*)&p2; ph[3] = *(uint32_t*)&p3;
            #pragma unroll
            for (int dt = 0; dt < 4; dt++) {
                uint32_t off = SWZ((uint32_t)((kk*16 + v_row)*128 + dt*32 + v_c16*16));
                uint32_t bvh[4];
                ldmx4t(bvh, vbh + off);
                mma16816(oacc[2*dt],   ph, bvh);
                mma16816(oacc[2*dt+1], ph, bvh+2);
            }
        }

        if (kt + 1 < 16) {
            CP_WAIT(0);
            __syncthreads();
        }
    }

    // ---- epilogue: O /= l, write fp16 into activation layout ----
    float il0 = 1.f / l0, il1 = 1.f / l1;
    size_t row0 = (size_t)(b*T_ + qt*128 + qloc0) * D_ + h*HD;
    size_t row1 = (size_t)(b*T_ + qt*128 + qloc1) * D_ + h*HD;
    #pragma unroll
    for (int dt = 0; dt < 8; dt++) {
        int d = dt*8 + 2*tig;
        __half2 hv0 = __floats2half2_rn(oacc[dt][0]*il0, oacc[dt][1]*il0);
        __half2 hv1 = __floats2half2_rn(oacc[dt][2]*il1, oacc[dt][3]*il1);
        *(uint32_t*)(outh + row0 + d) = *(uint32_t*)&hv0;
        *(uint32_t*)(outh + row1 + d) = *(uint32_t*)&hv1;
    }
}

// ---------------------------------------------------------------------------
extern "C" void kernel_launch(void* const* d_in, const int* in_sizes, int n_in,
                              void* d_out, int out_size)
{
    const float* hs    = (const float*)d_in[0];
    const float* q_w   = (const float*)d_in[1];
    const float* q_b   = (const float*)d_in[2];
    const float* k_w   = (const float*)d_in[3];
    const float* k_b   = (const float*)d_in[4];
    const float* v_w   = (const float*)d_in[5];
    const float* v_b   = (const float*)d_in[6];
    const float* out_w = (const float*)d_in[7];
    const float* out_b = (const float*)d_in[8];
    const float* rel   = (const float*)d_in[9];
    const float* gc    = (const float*)d_in[10];
    const float* gw    = (const float*)d_in[11];
    const float* gb    = (const float*)d_in[12];

    __half *ahi, *whi;
    cudaGetSymbolAddress((void**)&ahi, g_a_hi);
    cudaGetSymbolAddress((void**)&whi, g_w_hi);

    cudaFuncSetAttribute(qkv_mma_kernel,
                         cudaFuncAttributeMaxDynamicSharedMemorySize, SMEMT);
    cudaFuncSetAttribute(out_mma_kernel,
                         cudaFuncAttributeMaxDynamicSharedMemorySize, SMEMT);
    cudaFuncSetAttribute(flash_kernel,
                         cudaFuncAttributeMaxDynamicSharedMemorySize, F_SMEMT);

    pb_kernel<<<8, 256>>>(rel);
    gate_kernel<<<(BH*T_)/256, 256>>>(hs, gw, gb, gc);

    // Convert weights (4) + hs (4 quarters) to fp16 in one launch
    cvt_kernel<<<dim3(D_*D_/4/256, 8), 256>>>(q_w, k_w, v_w, out_w, hs, whi, ahi);

    // Merged Q/K/V projection (1-term fp16, BK=64): one launch, 768 CTAs
    qkv_mma_kernel<<<dim3(24, 32), 256, SMEMT>>>(ahi, q_b, k_b, v_b);

    // Fused attention: writes ctx into g_a_hi
    flash_kernel<<<dim3(8, BH), 256, F_SMEMT>>>(ahi);

    // Output projection (1-term fp16, BK=64)
    out_mma_kernel<<<dim3(8, 32), 256, SMEMT>>>(ahi, out_b, (float*)d_out);
}

// round 17
// speedup vs baseline: 2.3166x; 1.0085x over previous
#include <cuda_runtime.h>
#include <cuda_fp16.h>
#include <math.h>
#include <stdint.h>

// Problem constants
#define B_  4
#define T_  1024
#define D_  1024
#define H_  16
#define HD  64
#define BH  (B_*H_)     // 64
#define M_  (B_*T_)     // 4096

// Scratch (static device globals — no allocation)
__device__ float g_gate[BH*T_];               // [bh][t]
__device__ float g_pb[H_*2048];               // [h][rel+1023]

// fp16 buffers
__device__ __half g_a_hi[(size_t)M_*D_];      // activations (hs, later ctx)
__device__ __half g_w_hi[(size_t)4*D_*D_];    // 4 weight matrices
// q/k/v in [bh][t][d]
__device__ __half g_qh[(size_t)BH*T_*HD];
__device__ __half g_kh[(size_t)BH*T_*HD];
__device__ __half g_vh[(size_t)BH*T_*HD];

// ---------------------------------------------------------------------------
// PTX helpers
// ---------------------------------------------------------------------------
__device__ __forceinline__ uint32_t smem_u32(const void* p) {
    uint32_t a;
    asm("{ .reg .u64 t; cvta.to.shared.u64 t, %1; cvt.u32.u64 %0, t; }" : "=r"(a) : "l"(p));
    return a;
}
__device__ __forceinline__ void ldmx4(uint32_t* r, uint32_t addr) {
    asm volatile("ldmatrix.sync.aligned.m8n8.x4.shared.b16 {%0,%1,%2,%3}, [%4];"
        : "=r"(r[0]), "=r"(r[1]), "=r"(r[2]), "=r"(r[3]) : "r"(addr));
}
__device__ __forceinline__ void ldmx4t(uint32_t* r, uint32_t addr) {
    asm volatile("ldmatrix.sync.aligned.m8n8.x4.trans.shared.b16 {%0,%1,%2,%3}, [%4];"
        : "=r"(r[0]), "=r"(r[1]), "=r"(r[2]), "=r"(r[3]) : "r"(addr));
}
__device__ __forceinline__ void mma16816(float* c, const uint32_t* a, const uint32_t* b) {
    asm volatile("mma.sync.aligned.m16n8k16.row.col.f32.f16.f16.f32 "
        "{%0,%1,%2,%3}, {%4,%5,%6,%7}, {%8,%9}, {%0,%1,%2,%3};"
        : "+f"(c[0]), "+f"(c[1]), "+f"(c[2]), "+f"(c[3])
        : "r"(a[0]), "r"(a[1]), "r"(a[2]), "r"(a[3]), "r"(b[0]), "r"(b[1]));
}
__device__ __forceinline__ void cpasync16(uint32_t dst, const void* src) {
    asm volatile("cp.async.cg.shared.global [%0], [%1], 16;" :: "r"(dst), "l"(src));
}
#define CP_COMMIT()  asm volatile("cp.async.commit_group;" ::: "memory")
#define CP_WAIT(n)   asm volatile("cp.async.wait_group %0;" :: "n"(n) : "memory")
#define SWZ(o) ((o) ^ (((o) >> 3) & 0x70))

// ---------------------------------------------------------------------------
// Convert fp32 -> fp16: 8 matrices of 1024x1024 (4 weights + 4 hs quarters)
// ---------------------------------------------------------------------------
__global__ void cvt_kernel(const float* __restrict__ w0,
                           const float* __restrict__ w1,
                           const float* __restrict__ w2,
                           const float* __restrict__ w3,
                           const float* __restrict__ hs,
                           __half* __restrict__ whi,
                           __half* __restrict__ ahi)
{
    const int mat = blockIdx.y;
    const size_t QSZ = (size_t)D_ * D_;
    const float* x;
    __half* dst;
    if (mat < 4) {
        x   = (mat == 0) ? w0 : (mat == 1) ? w1 : (mat == 2) ? w2 : w3;
        dst = whi + (size_t)mat * QSZ;
    } else {
        x   = hs + (size_t)(mat - 4) * QSZ;
        dst = ahi + (size_t)(mat - 4) * QSZ;
    }
    int i = blockIdx.x * blockDim.x + threadIdx.x;
    float4 v = ((const float4*)x)[i];
    __half2 h0 = __floats2half2_rn(v.x, v.y);
    __half2 h1 = __floats2half2_rn(v.z, v.w);
    ((uint32_t*)dst)[2*i+0] = *(uint32_t*)&h0;
    ((uint32_t*)dst)[2*i+1] = *(uint32_t*)&h1;
}

// ---------------------------------------------------------------------------
// mma.sync projection GEMM core: C = A·W^T (pure fp16, fp32 accum)
// BK = 64, 3-stage cp.async pipeline, one barrier per iteration.
// Final iteration uses CP_WAIT(0) (no successor group in flight).
// ---------------------------------------------------------------------------
#define SST    72                 // 64 data + 8 pad halves (144B row stride)
#define MAT_B  (128*SST*2)        // 18432
#define STG_B  (2*MAT_B)          // 36864
#define SMEMT  (3*STG_B)          // 110592 (x2 CTAs = 216 KB <= 228 KB/SM)

__device__ __forceinline__ void proj_tile(
    const __half* __restrict__ A,
    const __half* __restrict__ W,
    const float* __restrict__ bias,
    float* __restrict__ outf,
    __half* __restrict__ outh,
    float scale, int remap, int m0, int n0, char* sm)
{
    const uint32_t sb = smem_u32(sm);
    const int tid = threadIdx.x;
    const int lane = tid & 31, wid = tid >> 5;
    const int wm = (wid >> 2) * 64, wn = (wid & 3) * 32;

    const __half* gsrc[2];
    gsrc[0] = A + (size_t)m0 * D_;
    gsrc[1] = W + (size_t)n0 * D_;

    auto issue = [&](int kt, int s) {
        uint32_t sdst = sb + s * STG_B;
        #pragma unroll
        for (int mat = 0; mat < 2; mat++) {
            const __half* g = gsrc[mat] + kt * 64;
            #pragma unroll
            for (int i = 0; i < 4; i++) {
                int idx = tid + i * 256;           // 0..1023
                int r = idx >> 3, c = idx & 7;     // 128 rows x 8 chunks
                cpasync16(sdst + mat*MAT_B + (uint32_t)(r*SST + c*8)*2,
                          g + (size_t)r * D_ + c * 8);
            }
        }
        CP_COMMIT();
    };

    float acc[4][4][4];
    #pragma unroll
    for (int mt = 0; mt < 4; mt++)
        #pragma unroll
        for (int nt = 0; nt < 4; nt++)
            #pragma unroll
            for (int r = 0; r < 4; r++) acc[mt][nt][r] = 0.f;

    // Prologue: fill 2 of 3 stages
    issue(0, 0);
    issue(1, 1);

    const int ar   = lane & 15;
    const int ac8  = lane >> 4;
    const int brow = (lane & 7) | ((lane & 16) >> 1);
    const int bc8  = (lane >> 3) & 1;

    int s = 0;
    for (int kt = 0; kt < 16; kt++) {
        if (kt + 1 < 16) CP_WAIT(1);   // stage kt landed; kt+1 may be in flight
        else             CP_WAIT(0);   // last stage: nothing may remain in flight
        __syncthreads();               // also releases stage (s+2)%3 for rewrite

        if (kt + 2 < 16) {
            int ns = s + 2; if (ns >= 3) ns -= 3;
            issue(kt + 2, ns);
        }

        const uint32_t base = sb + s * STG_B;
        #pragma unroll
        for (int k16 = 0; k16 < 4; k16++) {
            uint32_t aH[4][4];
            #pragma unroll
            for (int mt = 0; mt < 4; mt++) {
                uint32_t off = (uint32_t)((wm + mt*16 + ar)*SST + k16*16 + ac8*8) * 2;
                ldmx4(aH[mt], base + 0*MAT_B + off);
            }
            #pragma unroll
            for (int np = 0; np < 2; np++) {
                uint32_t bh4[4];
                uint32_t off = (uint32_t)((wn + np*16 + brow)*SST + k16*16 + bc8*8) * 2;
                ldmx4(bh4, base + 1*MAT_B + off);
                #pragma unroll
                for (int mt = 0; mt < 4; mt++) {
                    mma16816(acc[mt][2*np],   aH[mt], bh4);
                    mma16816(acc[mt][2*np+1], aH[mt], bh4+2);
                }
            }
        }

        if (++s >= 3) s = 0;
    }

    const int tg = lane >> 2, tig = lane & 3;
    #pragma unroll
    for (int mt = 0; mt < 4; mt++)
        #pragma unroll
        for (int i2 = 0; i2 < 2; i2++) {
            int m = m0 + wm + mt*16 + tg + i2*8;
            #pragma unroll
            for (int nt = 0; nt < 4; nt++) {
                int n = n0 + wn + nt*8 + tig*2;
                float v0 = (acc[mt][nt][i2*2+0] + bias[n])   * scale;
                float v1 = (acc[mt][nt][i2*2+1] + bias[n+1]) * scale;
                if (remap) {
                    int b = m >> 10, t = m & 1023;
                    int h = n >> 6,  d = n & 63;
                    size_t off = (((size_t)(b*H_ + h)*T_ + t))*HD + d;
                    __half2 hv = __floats2half2_rn(v0, v1);
                    *(uint32_t*)(outh + off) = *(uint32_t*)&hv;
                } else {
                    *(float2*)(outf + (size_t)m*D_ + n) = make_float2(v0, v1);
                }
            }
        }
}

// Merged Q/K/V projection: grid.x = 24 (mat = x>>3, n-block = x&7), grid.y = 32.
__global__ __launch_bounds__(256, 2)
void qkv_mma_kernel(const __half* __restrict__ A,
                    const float* __restrict__ q_b,
                    const float* __restrict__ k_b,
                    const float* __restrict__ v_b)
{
    extern __shared__ char sm[];
    const int mat = blockIdx.x >> 3;
    const int n0  = (blockIdx.x & 7) * 128;
    const int m0  = blockIdx.y * 128;
    const size_t WSZ = (size_t)D_*D_;
    const float* bias = (mat == 0) ? q_b : (mat == 1) ? k_b : v_b;
    const float scale = (mat == 0) ? 0.125f : 1.0f;
    __half* outh = (mat == 0) ? g_qh : (mat == 1) ? g_kh : g_vh;

    proj_tile(A, g_w_hi + mat*WSZ, bias, nullptr, outh, scale, 1, m0, n0, sm);
}

// Output projection (fp32 out)
__global__ __launch_bounds__(256, 2)
void out_mma_kernel(const __half* __restrict__ A,
                    const float* __restrict__ bias,
                    float* __restrict__ out)
{
    extern __shared__ char sm[];
    const size_t WSZ = (size_t)D_*D_;
    proj_tile(A, g_w_hi + 3*WSZ, bias, out, nullptr, 1.0f, 0,
              blockIdx.y * 128, blockIdx.x * 128, sm);
}

// ---------------------------------------------------------------------------
// Position-bias LUT
// ---------------------------------------------------------------------------
__global__ void pb_kernel(const float* __restrict__ rel_embed)
{
    int d = blockIdx.x * blockDim.x + threadIdx.x;
    if (d >= 2047) return;
    int rel = d - 1023;
    int rb  = (rel > 0) ? 160 : 0;
    int rp  = rel < 0 ? -rel : rel;
    int bucket;
    if (rp < 80) {
        bucket = rb + rp;
    } else {
        float t = logf((float)rp / 80.0f) / logf(10.0f);
        t = t * 80.0f;
        float v = 80.0f + t;
        int bi = (int)v;
        bucket = rb + (bi < 159 ? bi : 159);
    }
    #pragma unroll
    for (int h = 0; h < H_; h++)
        g_pb[h*2048 + d] = rel_embed[bucket*H_ + h];
}

// ---------------------------------------------------------------------------
// Gate
// ---------------------------------------------------------------------------
__global__ void gate_kernel(const float* __restrict__ hs,
                            const float* __restrict__ gw,
                            const float* __restrict__ gb,
                            const float* __restrict__ gc)
{
    int idx = blockIdx.x * blockDim.x + threadIdx.x;
    if (idx >= BH*T_) return;
    int t  = idx & (T_-1);
    int bh = idx >> 10;
    int h  = bh & (H_-1);
    int b  = bh >> 4;

    const float4* x = (const float4*)(hs + ((size_t)(b*T_+t))*D_ + h*HD);
    float p[8];
    #pragma unroll
    for (int e = 0; e < 8; e++) p[e] = 0.f;
    #pragma unroll
    for (int i = 0; i < 16; i++) {
        float4 xv = x[i];
        #pragma unroll
        for (int e = 0; e < 8; e++) {
            const float* w = gw + e*HD + i*4;
            p[e] += xv.x*w[0] + xv.y*w[1] + xv.z*w[2] + xv.w*w[3];
        }
    }
    float pa = p[0]+p[1]+p[2]+p[3] + gb[0]+gb[1]+gb[2]+gb[3];
    float pbv= p[4]+p[5]+p[6]+p[7] + gb[4]+gb[5]+gb[6]+gb[7];
    float ga  = 1.f/(1.f + expf(-pa));
    float gbs = 1.f/(1.f + expf(-pbv));
    g_gate[idx] = ga * (gbs * gc[h] - 1.f) + 2.f;
}

// ---------------------------------------------------------------------------
// Fused flash attention — pure fp16 mma, 64-row KV tiles, 2 CTAs/SM.
// QK: Qh·Kh.  PV: Ph·Vh.
// ---------------------------------------------------------------------------
#define FQ_B      16384                 // 128 x 64 fp16 (Q)
#define FKV_B     8192                  // 64 x 64 fp16 (one matrix)
#define F_STG_B   (2*FKV_B)             // K, V = 16 KB
#define F_SM_KV   FQ_B
#define F_SM_PB   (F_SM_KV + 2*F_STG_B) // 49152
#define F_SMEMT   (F_SM_PB + 2*192*4)   // 50688

__global__ __launch_bounds__(256, 2)
void flash_kernel(__half* __restrict__ outh)
{
    extern __shared__ char sm[];
    const uint32_t sb = smem_u32(sm);
    float* pb_s = (float*)(sm + F_SM_PB);

    const int tid  = threadIdx.x;
    const int lane = tid & 31, w = tid >> 5;
    const int qt = blockIdx.x, bh = blockIdx.y;
    const int b = bh >> 4, h = bh & 15;
    const size_t bhoff = (size_t)bh * T_ * HD;

    const __half* gQh = g_qh + bhoff + (size_t)qt*128*HD;

    // ---- prologue: Q + KV stage 0 + pb slice 0 ----
    #pragma unroll
    for (int i = 0; i < 4; i++) {
        int idx = tid + i * 256;
        int r = idx >> 3, c = idx & 7;
        uint32_t off = SWZ((uint32_t)(r*128 + c*16));
        cpasync16(sb + off, gQh + r*HD + c*8);
    }
    {
        const __half* src[2] = { g_kh + bhoff, g_vh + bhoff };
        #pragma unroll
        for (int mat = 0; mat < 2; mat++)
            #pragma unroll
            for (int i = 0; i < 2; i++) {
                int idx = tid + i * 256;
                int r = idx >> 3, c = idx & 7;
                uint32_t off = SWZ((uint32_t)(r*128 + c*16));
                cpasync16(sb + F_SM_KV + mat*FKV_B + off, src[mat] + r*HD + c*8);
            }
    }
    CP_COMMIT();
    if (tid < 192) pb_s[tid] = g_pb[h*2048 - qt*128 + 896 + tid];
    CP_WAIT(0);
    __syncthreads();

    // ---- Q fragments (register resident) ----
    uint32_t aQh[4][4];
    {
        const int ar = lane & 15, ac8 = lane >> 4;
        #pragma unroll
        for (int k16 = 0; k16 < 4; k16++) {
            uint32_t off = SWZ((uint32_t)((w*16 + ar)*128 + k16*32 + ac8*16));
            ldmx4(aQh[k16], sb + off);
        }
    }

    const int tg = lane >> 2, tig = lane & 3;
    const int qloc0 = w*16 + tg, qloc1 = qloc0 + 8;
    const float gate0 = g_gate[bh*T_ + qt*128 + qloc0];
    const float gate1 = g_gate[bh*T_ + qt*128 + qloc1];

    float m0 = -1e30f, m1 = -1e30f, l0 = 0.f, l1 = 0.f;
    float oacc[8][4];
    #pragma unroll
    for (int dt = 0; dt < 8; dt++)
        #pragma unroll
        for (int r = 0; r < 4; r++) oacc[dt][r] = 0.f;

    const int kb_row = (lane & 7) | ((lane & 16) >> 1);
    const int kb_c16 = (lane >> 3) & 1;
    const int v_row  = lane & 15;
    const int v_c16  = lane >> 4;

    for (int kt = 0; kt < 16; kt++) {
        const int s = kt & 1;
        // prefetch next KV stage + pb slice
        if (kt + 1 < 16) {
            const size_t koff = bhoff + (size_t)(kt+1)*64*HD;
            const __half* src[2] = { g_kh + koff, g_vh + koff };
            uint32_t sdst = sb + F_SM_KV + (s^1)*F_STG_B;
            #pragma unroll
            for (int mat = 0; mat < 2; mat++)
                #pragma unroll
                for (int i = 0; i < 2; i++) {
                    int idx = tid + i * 256;
                    int r = idx >> 3, c = idx & 7;
                    uint32_t off = SWZ((uint32_t)(r*128 + c*16));
                    cpasync16(sdst + mat*FKV_B + off, src[mat] + r*HD + c*8);
                }
            CP_COMMIT();
            if (tid < 192)
                pb_s[(s^1)*192 + tid] = g_pb[h*2048 + (kt+1)*64 - qt*128 + 896 + tid];
        }

        // ---- S = Qh·Kh, 128q x 64k ----
        const uint32_t kbh = sb + F_SM_KV + s*F_STG_B;
        float sacc[8][4];
        #pragma unroll
        for (int j = 0; j < 8; j++)
            #pragma unroll
            for (int r = 0; r < 4; r++) sacc[j][r] = 0.f;

        #pragma unroll
        for (int k16 = 0; k16 < 4; k16++) {
            #pragma unroll
            for (int np = 0; np < 4; np++) {
                uint32_t off = SWZ((uint32_t)((np*16 + kb_row)*128 + k16*32 + kb_c16*16));
                uint32_t bkh[4];
                ldmx4(bkh, kbh + off);
                mma16816(sacc[2*np],   aQh[k16], bkh);
                mma16816(sacc[2*np+1], aQh[k16], bkh+2);
            }
        }

        // ---- bias + online softmax ----
        const float* pbc = pb_s + s*192;
        float mx0 = -1e30f, mx1 = -1e30f;
        #pragma unroll
        for (int j = 0; j < 8; j++) {
            int kl0 = j*8 + 2*tig;
            sacc[j][0] += gate0 * pbc[kl0     - qloc0 + 127];
            sacc[j][1] += gate0 * pbc[kl0 + 1 - qloc0 + 127];
            sacc[j][2] += gate1 * pbc[kl0     - qloc1 + 127];
            sacc[j][3] += gate1 * pbc[kl0 + 1 - qloc1 + 127];
            mx0 = fmaxf(mx0, fmaxf(sacc[j][0], sacc[j][1]));
            mx1 = fmaxf(mx1, fmaxf(sacc[j][2], sacc[j][3]));
        }
        mx0 = fmaxf(mx0, __shfl_xor_sync(0xffffffffu, mx0, 1));
        mx0 = fmaxf(mx0, __shfl_xor_sync(0xffffffffu, mx0, 2));
        mx1 = fmaxf(mx1, __shfl_xor_sync(0xffffffffu, mx1, 1));
        mx1 = fmaxf(mx1, __shfl_xor_sync(0xffffffffu, mx1, 2));

        float nm0 = fmaxf(m0, mx0), nm1 = fmaxf(m1, mx1);
        float sc0 = __expf(m0 - nm0), sc1 = __expf(m1 - nm1);
        m0 = nm0; m1 = nm1;

        float rs0 = 0.f, rs1 = 0.f;
        #pragma unroll
        for (int j = 0; j < 8; j++) {
            sacc[j][0] = __expf(sacc[j][0] - m0);
            sacc[j][1] = __expf(sacc[j][1] - m0);
            sacc[j][2] = __expf(sacc[j][2] - m1);
            sacc[j][3] = __expf(sacc[j][3] - m1);
            rs0 += sacc[j][0] + sacc[j][1];
            rs1 += sacc[j][2] + sacc[j][3];
        }
        rs0 += __shfl_xor_sync(0xffffffffu, rs0, 1);
        rs0 += __shfl_xor_sync(0xffffffffu, rs0, 2);
        rs1 += __shfl_xor_sync(0xffffffffu, rs1, 1);
        rs1 += __shfl_xor_sync(0xffffffffu, rs1, 2);
        l0 = l0 * sc0 + rs0;
        l1 = l1 * sc1 + rs1;

        #pragma unroll
        for (int dt = 0; dt < 8; dt++) {
            oacc[dt][0] *= sc0; oacc[dt][1] *= sc0;
            oacc[dt][2] *= sc1; oacc[dt][3] *= sc1;
        }

        // ---- O += Ph·Vh, 64k x 64d ----
        const uint32_t vbh = kbh + FKV_B;
        #pragma unroll
        for (int kk = 0; kk < 4; kk++) {
            uint32_t ph[4];
            __half2 p0 = __floats2half2_rn(sacc[2*kk][0],   sacc[2*kk][1]);
            __half2 p1 = __floats2half2_rn(sacc[2*kk][2],   sacc[2*kk][3]);
            __half2 p2 = __floats2half2_rn(sacc[2*kk+1][0], sacc[2*kk+1][1]);
            __half2 p3 = __floats2half2_rn(sacc[2*kk+1][2], sacc[2*kk+1][3]);
            ph[0] = *(uint32_t*)&p0; ph[1] = *(uint32_t*)&p1;
            ph[2] = *(uint32_t*)&p2; ph[3] = *(uint32_t*)&p3;
            #pragma unroll
            for (int dt = 0; dt < 4; dt++) {
                uint32_t off = SWZ((uint32_t)((kk*16 + v_row)*128 + dt*32 + v_c16*16));
                uint32_t bvh[4];
                ldmx4t(bvh, vbh + off);
                mma16816(oacc[2*dt],   ph, bvh);
                mma16816(oacc[2*dt+1], ph, bvh+2);
            }
        }

        if (kt + 1 < 16) {
            CP_WAIT(0);
            __syncthreads();
        }
    }

    // ---- epilogue: O /= l, write fp16 into activation layout ----
    float il0 = 1.f / l0, il1 = 1.f / l1;
    size_t row0 = (size_t)(b*T_ + qt*128 + qloc0) * D_ + h*HD;
    size_t row1 = (size_t)(b*T_ + qt*128 + qloc1) * D_ + h*HD;
    #pragma unroll
    for (int dt = 0; dt < 8; dt++) {
        int d = dt*8 + 2*tig;
        __half2 hv0 = __floats2half2_rn(oacc[dt][0]*il0, oacc[dt][1]*il0);
        __half2 hv1 = __floats2half2_rn(oacc[dt][2]*il1, oacc[dt][3]*il1);
        *(uint32_t*)(outh + row0 + d) = *(uint32_t*)&hv0;
        *(uint32_t*)(outh + row1 + d) = *(uint32_t*)&hv1;
    }
}

// ---------------------------------------------------------------------------
extern "C" void kernel_launch(void* const* d_in, const int* in_sizes, int n_in,
                              void* d_out, int out_size)
{
    const float* hs    = (const float*)d_in[0];
    const float* q_w   = (const float*)d_in[1];
    const float* q_b   = (const float*)d_in[2];
    const float* k_w   = (const float*)d_in[3];
    const float* k_b   = (const float*)d_in[4];
    const float* v_w   = (const float*)d_in[5];
    const float* v_b   = (const float*)d_in[6];
    const float* out_w = (const float*)d_in[7];
    const float* out_b = (const float*)d_in[8];
    const float* rel   = (const float*)d_in[9];
    const float* gc    = (const float*)d_in[10];
    const float* gw    = (const float*)d_in[11];
    const float* gb    = (const float*)d_in[12];

    __half *ahi, *whi;
    cudaGetSymbolAddress((void**)&ahi, g_a_hi);
    cudaGetSymbolAddress((void**)&whi, g_w_hi);

    cudaFuncSetAttribute(qkv_mma_kernel,
                         cudaFuncAttributeMaxDynamicSharedMemorySize, SMEMT);
    cudaFuncSetAttribute(out_mma_kernel,
                         cudaFuncAttributeMaxDynamicSharedMemorySize, SMEMT);
    cudaFuncSetAttribute(flash_kernel,
                         cudaFuncAttributeMaxDynamicSharedMemorySize, F_SMEMT);

    pb_kernel<<<8, 256>>>(rel);
    gate_kernel<<<(BH*T_)/256, 256>>>(hs, gw, gb, gc);

    // Convert weights (4) + hs (4 quarters) to fp16 in one launch
    cvt_kernel<<<dim3(D_*D_/4/256, 8), 256>>>(q_w, k_w, v_w, out_w, hs, whi, ahi);

    // Merged Q/K/V projection (1-term fp16, BK=64, 3-stage): 768 CTAs
    qkv_mma_kernel<<<dim3(24, 32), 256, SMEMT>>>(ahi, q_b, k_b, v_b);

    // Fused attention: writes ctx into g_a_hi
    flash_kernel<<<dim3(8, BH), 256, F_SMEMT>>>(ahi);

    // Output projection (1-term fp16, BK=64, 3-stage)
    out_mma_kernel<<<dim3(8, 32), 256, SMEMT>>>(ahi, out_b, (float*)d_out);
}